// round 6
// baseline (speedup 1.0000x reference)
#include <cuda_runtime.h>

// ---------------- problem constants ----------------
#define NPTS   32768        // B*P
#define PP     1024         // points per sample
#define NB     32           // batch
#define FF     64           // feature dim
#define KK     32           // max neighbors
#define C1     128          // hidden dim
#define STATB  1024         // stat partial blocks (32 queries each)
#define HSTRIDE 72          // padded edge stride for h staging in smem
#define ENC_NEG_INF 0x007FFFFFu

// ---------------- device scratch (static, no allocation) ----------------
__device__ float    g_Y[NPTS * C1];         // x @ W1[:64]   (16 MB)
__device__ int      g_pix[NPTS];            // pixel (target) index per point
__device__ int      g_nbr[NPTS * KK];       // valid neighbor global idx or -1
__device__ float    g_psum[STATB * C1];
__device__ float    g_psq [STATB * C1];
__device__ int      g_pcnt[STATB];
__device__ float    g_coef[4 * C1];         // alpha | w64*alpha | w65*alpha | beta+(b1-mean)*alpha

// monotone float<->uint encoding for atomicMax on floats
__device__ __forceinline__ unsigned encf(float f) {
    unsigned u = __float_as_uint(f);
    return (u & 0x80000000u) ? ~u : (u | 0x80000000u);
}
__device__ __forceinline__ float decf(unsigned u) {
    return (u & 0x80000000u) ? __uint_as_float(u & 0x7fffffffu)
                             : __uint_as_float(~u);
}

// ---------------- kernel 0: init output accumulator ----------------
__global__ void k_init(unsigned* __restrict__ out_u) {
    int i = blockIdx.x * 256 + threadIdx.x;
    if (i < NPTS * FF) out_u[i] = ENC_NEG_INF;
}

// ---------------- kernel 1: pixel index + Y = x @ W1[:64] ----------------
// 512 blocks x 256 threads, 64 points per block.
__global__ void k_pre(const float* __restrict__ x, const float* __restrict__ pos,
                      const int* __restrict__ batch, const float* __restrict__ W1) {
    __shared__ float w1s[64 * C1];   // 32 KB
    __shared__ float xs[64 * FF];    // 16 KB
    int tid = threadIdx.x;
    int p0 = blockIdx.x * 64;

    for (int i = tid; i < 64 * C1; i += 256) w1s[i] = W1[i];
    for (int i = tid; i < 64 * FF; i += 256) xs[i] = x[p0 * FF + i];
    if (tid < 64) {
        int i = p0 + tid;
        float px = pos[2 * i], py = pos[2 * i + 1];
        int col = (int)(px * 32.0f); col = min(max(col, 0), 31);
        int row = (int)(py * 32.0f); row = min(max(row, 0), 31);
        g_pix[i] = batch[i] * (NB * NB) + row * 32 + col;
    }
    __syncthreads();

    int pg = tid >> 5;          // 8 point-groups of 8 points
    int cg = tid & 31;          // 32 channel-groups of 4 channels
    int c0 = cg * 4;
    float acc[8][4];
#pragma unroll
    for (int p = 0; p < 8; p++)
#pragma unroll
        for (int c = 0; c < 4; c++) acc[p][c] = 0.f;

    for (int r = 0; r < 64; r++) {
        float4 w = *(const float4*)&w1s[r * C1 + c0];
#pragma unroll
        for (int p = 0; p < 8; p++) {
            float xv = xs[(pg * 8 + p) * FF + r];
            acc[p][0] = fmaf(xv, w.x, acc[p][0]);
            acc[p][1] = fmaf(xv, w.y, acc[p][1]);
            acc[p][2] = fmaf(xv, w.z, acc[p][2]);
            acc[p][3] = fmaf(xv, w.w, acc[p][3]);
        }
    }
#pragma unroll
    for (int p = 0; p < 8; p++) {
        int pt = p0 + pg * 8 + p;
        float4 v = make_float4(acc[p][0], acc[p][1], acc[p][2], acc[p][3]);
        *(float4*)&g_Y[pt * C1 + c0] = v;
    }
}

// ---------------- kernel 2: radius ball-query, K nearest ----------------
// 128 blocks x 256 threads; block handles 256 queries of one batch sample.
// Matches jax.lax.top_k(-d2, 32): K smallest d2 (<=R^2), ties -> lowest index.
// d2 computed with rn mul/add (no FMA contraction) to bit-match reference.
__global__ void k_nbr(const float* __restrict__ pos) {
    __shared__ float2 ps[PP];
    int tid = threadIdx.x;
    int b = blockIdx.x >> 2;
    const float2* pb = (const float2*)pos + b * PP;
    for (int i = tid; i < PP; i += 256) ps[i] = pb[i];
    __syncthreads();

    int ql = ((blockIdx.x & 3) << 8) + tid;
    int q = b * PP + ql;
    float qx = ps[ql].x, qy = ps[ql].y;
    const float R2 = 0.01f;          // (float)(0.1*0.1)
    const float INF = __int_as_float(0x7f800000);

    // threshold pass: keep 32 smallest d2 values (replace-max scheme)
    float best[32];
#pragma unroll
    for (int k = 0; k < 32; k++) best[k] = INF;
    float bmax = INF; int bpos = 0;

    for (int j = 0; j < PP; j++) {
        float dx = __fsub_rn(qx, ps[j].x);
        float dy = __fsub_rn(qy, ps[j].y);
        float d2 = __fadd_rn(__fmul_rn(dx, dx), __fmul_rn(dy, dy));
        if (d2 <= R2 && d2 < bmax) {
#pragma unroll
            for (int k = 0; k < 32; k++) best[k] = (k == bpos) ? d2 : best[k];
            float m = best[0]; int mp = 0;
#pragma unroll
            for (int k = 1; k < 32; k++) { if (best[k] > m) { m = best[k]; mp = k; } }
            bmax = m; bpos = mp;
        }
    }
    float t = bmax;  // 32nd-smallest d2, or INF if fewer than 32 in radius

    // count strictly-below-threshold
    int c1 = 0;
    for (int j = 0; j < PP; j++) {
        float dx = __fsub_rn(qx, ps[j].x);
        float dy = __fsub_rn(qy, ps[j].y);
        float d2 = __fadd_rn(__fmul_rn(dx, dx), __fmul_rn(dy, dy));
        c1 += (d2 <= R2 && d2 < t) ? 1 : 0;
    }
    int quota = 32 - c1;        // ties at t taken by ascending index
    int pixq = g_pix[q];
    int kout = 0;

    for (int j = 0; j < PP; j++) {
        float dx = __fsub_rn(qx, ps[j].x);
        float dy = __fsub_rn(qy, ps[j].y);
        float d2 = __fadd_rn(__fmul_rn(dx, dx), __fmul_rn(dy, dy));
        if (d2 > R2) continue;
        bool take = false;
        if (d2 < t) take = true;
        else if (d2 == t && quota > 0) { take = true; quota--; }
        if (take) {
            int s = b * PP + j;
            if (s != pixq)                       // remove_self_loops (src == mapped dst)
                g_nbr[q * KK + (kout++)] = s;
        }
    }
    for (; kout < KK; kout++) g_nbr[q * KK + kout] = -1;
}

// ---------------- kernel 3: BN partial stats (deterministic, no atomics) ----
// 1024 blocks x 128 threads; block covers 32 queries (1024 edge slots + 32 self msgs).
__global__ void k_stats(const float* __restrict__ pos, const float* __restrict__ W1,
                        const float* __restrict__ b1) {
    __shared__ int   es[1056];
    __shared__ float ex[1056];
    __shared__ float ey[1056];
    int tid = threadIdx.x;
    int q0 = blockIdx.x * 32;

    for (int idx = tid; idx < 1024; idx += 128) {
        int q = q0 + (idx >> 5);
        int s = g_nbr[q * KK + (idx & 31)];
        es[idx] = s;
        float rx = 0.f, ry = 0.f;
        if (s >= 0) {
            int d = g_pix[q];
            rx = pos[2 * s]     - pos[2 * d];
            ry = pos[2 * s + 1] - pos[2 * d + 1];
        }
        ex[idx] = rx; ey[idx] = ry;
    }
    if (tid < 32) { es[1024 + tid] = q0 + tid; ex[1024 + tid] = 0.f; ey[1024 + tid] = 0.f; }
    __syncthreads();

    int c = tid;
    float w64 = W1[64 * C1 + c], w65 = W1[65 * C1 + c], b1c = b1[c];
    float sum = 0.f, sq = 0.f;
    int cnt = 0;
    for (int e = 0; e < 1056; e++) {
        int s = es[e];
        if (s < 0) continue;
        cnt++;
        float z = g_Y[s * C1 + c] + ex[e] * w64 + ey[e] * w65 + b1c;
        sum += z;
        sq = fmaf(z, z, sq);
    }
    g_psum[blockIdx.x * C1 + c] = sum;
    g_psq [blockIdx.x * C1 + c] = sq;
    if (tid == 0) g_pcnt[blockIdx.x] = cnt;
}

// ---------------- kernel 4: reduce stats -> fused BN coefficients ----------
__global__ void k_reduce(const float* __restrict__ W1, const float* __restrict__ b1,
                         const float* __restrict__ gamma1, const float* __restrict__ beta1) {
    int c = threadIdx.x;
    double s = 0.0, ss = 0.0;
    long long cnt = 0;
    for (int b = 0; b < STATB; b++) {
        s  += (double)g_psum[b * C1 + c];
        ss += (double)g_psq [b * C1 + c];
        cnt += g_pcnt[b];
    }
    double mean = s / (double)cnt;
    double var  = ss / (double)cnt - mean * mean;
    float A = gamma1[c] / sqrtf((float)var + 1e-5f);
    g_coef[c]           = A;
    g_coef[C1 + c]      = W1[64 * C1 + c] * A;
    g_coef[2 * C1 + c]  = W1[65 * C1 + c] * A;
    g_coef[3 * C1 + c]  = beta1[c] + (b1[c] - (float)mean) * A;
}

// ---------------- shared-memory layout for the GEMM2 kernels --------------
// [W2s 8192][hs 128*72][cfA 128][cfX 128][cfY 128][cfB 128][b2s 64]
// [ex2 64][ey2 64][es2 64(int)][qmx 128(uint)]
#define SMEM_FLOATS (8192 + C1*HSTRIDE + 4*C1 + 64 + 64 + 64 + 64 + 128)
#define SMEM_BYTES  (SMEM_FLOATS * 4)

// ---------------- kernel 5: main fused GEMM2 + local max + scatter --------
// 16384 blocks x 128 threads; 2 queries (64 edge slots) per block.
__global__ void k_main(const float* __restrict__ pos, const float* __restrict__ W2,
                       const float* __restrict__ b2, unsigned* __restrict__ out_u) {
    extern __shared__ float sm[];
    float*    W2s = sm;
    float*    hs  = sm + 8192;
    float*    cfA = sm + 8192 + C1 * HSTRIDE;
    float*    cfX = cfA + C1;
    float*    cfY = cfX + C1;
    float*    cfB = cfY + C1;
    float*    b2s = cfB + C1;
    float*    ex2 = b2s + 64;
    float*    ey2 = ex2 + 64;
    int*      es2 = (int*)(ey2 + 64);
    unsigned* qmx = (unsigned*)(es2 + 64);

    int tid = threadIdx.x;
    int q0 = blockIdx.x * 2;

    for (int i = tid; i < 8192; i += 128) W2s[i] = W2[i];
    cfA[tid] = g_coef[tid];
    cfX[tid] = g_coef[C1 + tid];
    cfY[tid] = g_coef[2 * C1 + tid];
    cfB[tid] = g_coef[3 * C1 + tid];
    if (tid < 64) b2s[tid] = b2[tid];
    if (tid < 64) {
        int q = q0 + (tid >> 5);
        int s = g_nbr[q * KK + (tid & 31)];
        es2[tid] = s;
        float rx = 0.f, ry = 0.f;
        if (s >= 0) {
            int d = g_pix[q];
            rx = pos[2 * s]     - pos[2 * d];
            ry = pos[2 * s + 1] - pos[2 * d + 1];
        }
        ex2[tid] = rx; ey2[tid] = ry;
    }
    qmx[tid] = ENC_NEG_INF;
    __syncthreads();

    // h phase: thread == channel
    {
        float a = cfA[tid], wx = cfX[tid], wy = cfY[tid], bb = cfB[tid];
#pragma unroll 4
        for (int e = 0; e < 64; e++) {
            int s = es2[e];
            float h = 0.f;
            if (s >= 0) {
                float z = fmaf(g_Y[s * C1 + tid], a,
                          fmaf(ex2[e], wx, fmaf(ey2[e], wy, bb)));
                h = fmaxf(z, 0.f);
            }
            hs[tid * HSTRIDE + e] = h;
        }
    }
    __syncthreads();

    // o phase: 4-edge x 8-channel register tiles
    int eg = tid & 15, fg = tid >> 4;
    float acc[4][8];
#pragma unroll
    for (int e = 0; e < 4; e++)
#pragma unroll
        for (int f = 0; f < 8; f++) acc[e][f] = 0.f;

    const float* hb = hs + eg * 4;
    const float* wb = W2s + fg * 8;
    for (int c = 0; c < C1; c++) {
        float4 hv = *(const float4*)(hb + c * HSTRIDE);
        float4 w0 = *(const float4*)(wb + c * 64);
        float4 w1 = *(const float4*)(wb + c * 64 + 4);
        float hvv[4] = {hv.x, hv.y, hv.z, hv.w};
        float wv[8]  = {w0.x, w0.y, w0.z, w0.w, w1.x, w1.y, w1.z, w1.w};
#pragma unroll
        for (int e = 0; e < 4; e++)
#pragma unroll
            for (int f = 0; f < 8; f++)
                acc[e][f] = fmaf(hvv[e], wv[f], acc[e][f]);
    }

    // masked max over this thread's 4 edges, fold into per-query smem max
    int qloc = eg >> 3;
    const float NINF = __int_as_float(0xff800000);
#pragma unroll
    for (int f = 0; f < 8; f++) {
        float bv = b2s[fg * 8 + f];
        float m = NINF;
#pragma unroll
        for (int e = 0; e < 4; e++)
            if (es2[eg * 4 + e] >= 0) m = fmaxf(m, acc[e][f] + bv);
        atomicMax(&qmx[qloc * 64 + fg * 8 + f], encf(m));
    }
    __syncthreads();

    // one global atomic per (query, channel)
    {
        unsigned v = qmx[tid];
        if (v != ENC_NEG_INF) {
            int q = q0 + (tid >> 6);
            int P = g_pix[q];
            atomicMax(&out_u[(P >> 10) * (FF * PP) + (tid & 63) * PP + (P & 1023)], v);
        }
    }
}

// ---------------- kernel 6: self-loop messages (target = own node index) ---
// 512 blocks x 128 threads; 64 nodes per block.
__global__ void k_self(const float* __restrict__ W2, const float* __restrict__ b2,
                       unsigned* __restrict__ out_u) {
    extern __shared__ float sm[];
    float* W2s = sm;
    float* hs  = sm + 8192;
    float* cfA = sm + 8192 + C1 * HSTRIDE;
    float* cfB = cfA + C1;
    float* b2s = cfB + C1;

    int tid = threadIdx.x;
    int i0 = blockIdx.x * 64;

    for (int i = tid; i < 8192; i += 128) W2s[i] = W2[i];
    cfA[tid] = g_coef[tid];
    cfB[tid] = g_coef[3 * C1 + tid];
    if (tid < 64) b2s[tid] = b2[tid];
    __syncthreads();

    {
        float a = cfA[tid], bb = cfB[tid];
#pragma unroll 4
        for (int e = 0; e < 64; e++)
            hs[tid * HSTRIDE + e] = fmaxf(fmaf(g_Y[(i0 + e) * C1 + tid], a, bb), 0.f);
    }
    __syncthreads();

    int eg = tid & 15, fg = tid >> 4;
    float acc[4][8];
#pragma unroll
    for (int e = 0; e < 4; e++)
#pragma unroll
        for (int f = 0; f < 8; f++) acc[e][f] = 0.f;

    const float* hb = hs + eg * 4;
    const float* wb = W2s + fg * 8;
    for (int c = 0; c < C1; c++) {
        float4 hv = *(const float4*)(hb + c * HSTRIDE);
        float4 w0 = *(const float4*)(wb + c * 64);
        float4 w1 = *(const float4*)(wb + c * 64 + 4);
        float hvv[4] = {hv.x, hv.y, hv.z, hv.w};
        float wv[8]  = {w0.x, w0.y, w0.z, w0.w, w1.x, w1.y, w1.z, w1.w};
#pragma unroll
        for (int e = 0; e < 4; e++)
#pragma unroll
            for (int f = 0; f < 8; f++)
                acc[e][f] = fmaf(hvv[e], wv[f], acc[e][f]);
    }

#pragma unroll
    for (int e = 0; e < 4; e++) {
        int node = i0 + eg * 4 + e;
        unsigned base = (unsigned)((node >> 10) * (FF * PP) + (node & 1023));
#pragma unroll
        for (int f = 0; f < 8; f++) {
            float v = acc[e][f] + b2s[fg * 8 + f];
            atomicMax(&out_u[base + (fg * 8 + f) * PP], encf(v));
        }
    }
}

// ---------------- kernel 7: decode in place ----------------
__global__ void k_decode(unsigned* __restrict__ out_u) {
    int i = blockIdx.x * 256 + threadIdx.x;
    if (i < NPTS * FF) {
        unsigned u = out_u[i];
        ((float*)out_u)[i] = decf(u);
    }
}

// ---------------- launch ----------------
extern "C" void kernel_launch(void* const* d_in, const int* in_sizes, int n_in,
                              void* d_out, int out_size) {
    const float* x      = (const float*)d_in[0];
    const float* pos    = (const float*)d_in[1];
    const int*   batch  = (const int*)  d_in[2];
    const float* W1     = (const float*)d_in[3];
    const float* b1     = (const float*)d_in[4];
    const float* gamma1 = (const float*)d_in[5];
    const float* beta1  = (const float*)d_in[6];
    const float* W2     = (const float*)d_in[7];
    const float* b2     = (const float*)d_in[8];
    unsigned* out_u = (unsigned*)d_out;

    cudaFuncSetAttribute(k_main, cudaFuncAttributeMaxDynamicSharedMemorySize, SMEM_BYTES);
    cudaFuncSetAttribute(k_self, cudaFuncAttributeMaxDynamicSharedMemorySize, SMEM_BYTES);

    k_init  <<<(NPTS * FF + 255) / 256, 256>>>(out_u);
    k_pre   <<<NPTS / 64, 256>>>(x, pos, batch, W1);
    k_nbr   <<<NB * 4, 256>>>(pos);
    k_stats <<<STATB, 128>>>(pos, W1, b1);
    k_reduce<<<1, 128>>>(W1, b1, gamma1, beta1);
    k_main  <<<NPTS / 2, 128, SMEM_BYTES>>>(pos, W2, b2, out_u);
    k_self  <<<NPTS / 64, 128, SMEM_BYTES>>>(W2, b2, out_u);
    k_decode<<<(NPTS * FF + 255) / 256, 256>>>(out_u);
}

// round 7
// speedup vs baseline: 1.0790x; 1.0790x over previous
#include <cuda_runtime.h>

// ---------------- problem constants ----------------
#define NPTS   32768        // B*P
#define PP     1024         // points per sample
#define NB     32           // batch
#define FF     64           // feature dim
#define KK     32           // max neighbors
#define C1     128          // hidden dim
#define STATB  1024         // stat blocks (32 queries each, 2 partials per block)
#define ENC_NEG_INF 0x007FFFFFu

#define HS 132              // h smem stride (edge-major)
#define WS 72               // W2 smem stride
// k_main smem floats: hs 128*132 | W2s 128*72 | cfA/X/Y/B 4*128 | b2s 64 | ex2 128 | ey2 128 | es2 128(int) | qmx 256
#define SMEM_MAIN_FLOATS (128*HS + 128*WS + 4*C1 + 64 + 128 + 128 + 128 + 256)
#define SMEM_MAIN_BYTES  (SMEM_MAIN_FLOATS * 4)

// k_self smem: W2s 8192 | hs 128*72 | cfA 128 | cfB 128 | b2s 64
#define HSTR2 72
#define SMEM_SELF_FLOATS (8192 + 128*HSTR2 + 128 + 128 + 64)
#define SMEM_SELF_BYTES  (SMEM_SELF_FLOATS * 4)

// ---------------- device scratch (static, no allocation) ----------------
__device__ float    g_Y[NPTS * C1];         // x @ W1[:64]  (16 MB)
__device__ int      g_pix[NPTS];
__device__ int      g_nbr[NPTS * KK];
__device__ float    g_psum[2 * STATB * C1];
__device__ float    g_psq [2 * STATB * C1];
__device__ int      g_pcnt[2 * STATB];
__device__ float    g_coef[4 * C1];         // alpha | w64*a | w65*a | beta+(b1-mean)*a

__device__ __forceinline__ unsigned encf(float f) {
    unsigned u = __float_as_uint(f);
    return (u & 0x80000000u) ? ~u : (u | 0x80000000u);
}
__device__ __forceinline__ float decf(unsigned u) {
    return (u & 0x80000000u) ? __uint_as_float(u & 0x7fffffffu)
                             : __uint_as_float(~u);
}
__device__ __forceinline__ unsigned f2tf32(float f) {
    unsigned u;
    asm("cvt.rna.tf32.f32 %0, %1;" : "=r"(u) : "f"(f));
    return u;
}

// ---------------- kernel 0: init output accumulator ----------------
__global__ void k_init(unsigned* __restrict__ out_u) {
    int i = blockIdx.x * 256 + threadIdx.x;
    if (i < NPTS * FF) out_u[i] = ENC_NEG_INF;
}

// ---------------- kernel 1: pixel index + Y = x @ W1[:64] ----------------
__global__ void k_pre(const float* __restrict__ x, const float* __restrict__ pos,
                      const int* __restrict__ batch, const float* __restrict__ W1) {
    __shared__ float w1s[64 * C1];
    __shared__ float xs[64 * FF];
    int tid = threadIdx.x;
    int p0 = blockIdx.x * 64;

    for (int i = tid; i < 64 * C1; i += 256) w1s[i] = W1[i];
    for (int i = tid; i < 64 * FF; i += 256) xs[i] = x[p0 * FF + i];
    if (tid < 64) {
        int i = p0 + tid;
        float px = pos[2 * i], py = pos[2 * i + 1];
        int col = (int)(px * 32.0f); col = min(max(col, 0), 31);
        int row = (int)(py * 32.0f); row = min(max(row, 0), 31);
        g_pix[i] = batch[i] * (NB * NB) + row * 32 + col;
    }
    __syncthreads();

    int pg = tid >> 5;
    int c0 = (tid & 31) * 4;
    float acc[8][4];
#pragma unroll
    for (int p = 0; p < 8; p++)
#pragma unroll
        for (int c = 0; c < 4; c++) acc[p][c] = 0.f;

    for (int r = 0; r < 64; r++) {
        float4 w = *(const float4*)&w1s[r * C1 + c0];
#pragma unroll
        for (int p = 0; p < 8; p++) {
            float xv = xs[(pg * 8 + p) * FF + r];
            acc[p][0] = fmaf(xv, w.x, acc[p][0]);
            acc[p][1] = fmaf(xv, w.y, acc[p][1]);
            acc[p][2] = fmaf(xv, w.z, acc[p][2]);
            acc[p][3] = fmaf(xv, w.w, acc[p][3]);
        }
    }
#pragma unroll
    for (int p = 0; p < 8; p++) {
        int pt = p0 + pg * 8 + p;
        *(float4*)&g_Y[pt * C1 + c0] =
            make_float4(acc[p][0], acc[p][1], acc[p][2], acc[p][3]);
    }
}

// ---------------- kernel 2: radius ball-query, K nearest ----------------
__global__ void k_nbr(const float* __restrict__ pos) {
    __shared__ float2 ps[PP];
    int tid = threadIdx.x;
    int b = blockIdx.x >> 2;
    const float2* pb = (const float2*)pos + b * PP;
    for (int i = tid; i < PP; i += 256) ps[i] = pb[i];
    __syncthreads();

    int ql = ((blockIdx.x & 3) << 8) + tid;
    int q = b * PP + ql;
    float qx = ps[ql].x, qy = ps[ql].y;
    const float R2 = 0.01f;
    const float INF = __int_as_float(0x7f800000);

    float best[32];
#pragma unroll
    for (int k = 0; k < 32; k++) best[k] = INF;
    float bmax = INF; int bpos = 0;

    for (int j = 0; j < PP; j++) {
        float dx = __fsub_rn(qx, ps[j].x);
        float dy = __fsub_rn(qy, ps[j].y);
        float d2 = __fadd_rn(__fmul_rn(dx, dx), __fmul_rn(dy, dy));
        if (d2 <= R2 && d2 < bmax) {
#pragma unroll
            for (int k = 0; k < 32; k++) best[k] = (k == bpos) ? d2 : best[k];
            // depth-5 tree argmax (issue-bound, not a serial dep chain)
            float m16[16]; int i16[16];
#pragma unroll
            for (int k = 0; k < 16; k++) {
                bool p = best[2*k] >= best[2*k+1];
                m16[k] = p ? best[2*k] : best[2*k+1];
                i16[k] = p ? 2*k : 2*k+1;
            }
            float m8[8]; int i8[8];
#pragma unroll
            for (int k = 0; k < 8; k++) {
                bool p = m16[2*k] >= m16[2*k+1];
                m8[k] = p ? m16[2*k] : m16[2*k+1];
                i8[k] = p ? i16[2*k] : i16[2*k+1];
            }
            float m4[4]; int i4[4];
#pragma unroll
            for (int k = 0; k < 4; k++) {
                bool p = m8[2*k] >= m8[2*k+1];
                m4[k] = p ? m8[2*k] : m8[2*k+1];
                i4[k] = p ? i8[2*k] : i8[2*k+1];
            }
            float m2[2]; int i2[2];
#pragma unroll
            for (int k = 0; k < 2; k++) {
                bool p = m4[2*k] >= m4[2*k+1];
                m2[k] = p ? m4[2*k] : m4[2*k+1];
                i2[k] = p ? i4[2*k] : i4[2*k+1];
            }
            bool p = m2[0] >= m2[1];
            bmax = p ? m2[0] : m2[1];
            bpos = p ? i2[0] : i2[1];
        }
    }
    float t = bmax;

    int c1 = 0;
    for (int j = 0; j < PP; j++) {
        float dx = __fsub_rn(qx, ps[j].x);
        float dy = __fsub_rn(qy, ps[j].y);
        float d2 = __fadd_rn(__fmul_rn(dx, dx), __fmul_rn(dy, dy));
        c1 += (d2 <= R2 && d2 < t) ? 1 : 0;
    }
    int quota = 32 - c1;
    int pixq = g_pix[q];
    int kout = 0;

    for (int j = 0; j < PP; j++) {
        float dx = __fsub_rn(qx, ps[j].x);
        float dy = __fsub_rn(qy, ps[j].y);
        float d2 = __fadd_rn(__fmul_rn(dx, dx), __fmul_rn(dy, dy));
        if (d2 > R2) continue;
        bool take = false;
        if (d2 < t) take = true;
        else if (d2 == t && quota > 0) { take = true; quota--; }
        if (take) {
            int s = b * PP + j;
            if (s != pixq) g_nbr[q * KK + (kout++)] = s;
        }
    }
    for (; kout < KK; kout++) g_nbr[q * KK + kout] = -1;
}

// ---------------- kernel 3: BN partial stats (deterministic, split halves) --
__global__ void k_stats(const float* __restrict__ pos, const float* __restrict__ W1,
                        const float* __restrict__ b1) {
    __shared__ int   es[1056];
    __shared__ float ex[1056];
    __shared__ float ey[1056];
    int tid = threadIdx.x;
    int q0 = blockIdx.x * 32;

    for (int idx = tid; idx < 1024; idx += 256) {
        int q = q0 + (idx >> 5);
        int s = g_nbr[q * KK + (idx & 31)];
        es[idx] = s;
        float rx = 0.f, ry = 0.f;
        if (s >= 0) {
            int d = g_pix[q];
            rx = pos[2 * s]     - pos[2 * d];
            ry = pos[2 * s + 1] - pos[2 * d + 1];
        }
        ex[idx] = rx; ey[idx] = ry;
    }
    if (tid < 32) { es[1024 + tid] = q0 + tid; ex[1024 + tid] = 0.f; ey[1024 + tid] = 0.f; }
    __syncthreads();

    int c = tid & 127;
    int half = tid >> 7;
    int eb = half * 528;
    float w64 = W1[64 * C1 + c], w65 = W1[65 * C1 + c], b1c = b1[c];
    float sum = 0.f, sq = 0.f;
    int cnt = 0;
#pragma unroll 4
    for (int e = eb; e < eb + 528; e++) {
        int s = es[e];
        if (s < 0) continue;
        cnt++;
        float z = g_Y[s * C1 + c] + ex[e] * w64 + ey[e] * w65 + b1c;
        sum += z;
        sq = fmaf(z, z, sq);
    }
    int slot = blockIdx.x * 2 + half;
    g_psum[slot * C1 + c] = sum;
    g_psq [slot * C1 + c] = sq;
    if ((tid & 127) == 0) g_pcnt[slot] = cnt;
}

// ---------------- kernel 4: reduce stats -> fused BN coefficients ----------
__global__ void k_reduce(const float* __restrict__ W1, const float* __restrict__ b1,
                         const float* __restrict__ gamma1, const float* __restrict__ beta1) {
    int c = threadIdx.x;
    double s0 = 0, s1 = 0, q0 = 0, q1 = 0;
    long long cnt = 0;
    for (int b = 0; b < 2 * STATB; b += 2) {
        s0 += (double)g_psum[b * C1 + c];
        s1 += (double)g_psum[(b + 1) * C1 + c];
        q0 += (double)g_psq [b * C1 + c];
        q1 += (double)g_psq [(b + 1) * C1 + c];
        cnt += g_pcnt[b] + g_pcnt[b + 1];
    }
    double mean = (s0 + s1) / (double)cnt;
    double var  = (q0 + q1) / (double)cnt - mean * mean;
    float A = gamma1[c] / sqrtf((float)var + 1e-5f);
    g_coef[c]           = A;
    g_coef[C1 + c]      = W1[64 * C1 + c] * A;
    g_coef[2 * C1 + c]  = W1[65 * C1 + c] * A;
    g_coef[3 * C1 + c]  = beta1[c] + (b1[c] - (float)mean) * A;
}

// ---------------- kernel 5: main fused (h -> tf32 mma GEMM2 -> max scatter) -
// 8192 blocks x 256 threads; 4 queries (128 edge slots) per block.
__global__ void __launch_bounds__(256, 2)
k_main(const float* __restrict__ pos, const float* __restrict__ W2,
       const float* __restrict__ b2, unsigned* __restrict__ out_u) {
    extern __shared__ float sm[];
    float* hs  = sm;                        // tf32 bits, edge-major [128][HS]
    float* W2s = sm + 128 * HS;             // fp32 [128][WS]
    float* cfA = W2s + 128 * WS;
    float* cfX = cfA + C1;
    float* cfY = cfX + C1;
    float* cfB = cfY + C1;
    float* b2s = cfB + C1;
    float* ex2 = b2s + 64;
    float* ey2 = ex2 + 128;
    int*   es2 = (int*)(ey2 + 128);
    float* qmx = (float*)(es2 + 128);       // [4 queries][64 cols]

    int tid = threadIdx.x;
    int q0 = blockIdx.x * 4;
    const float NI = __int_as_float(0xff800000);

    for (int i = tid; i < 8192; i += 256) W2s[(i >> 6) * WS + (i & 63)] = W2[i];
    if (tid < 128) {
        cfA[tid] = g_coef[tid];
        cfX[tid] = g_coef[C1 + tid];
        cfY[tid] = g_coef[2 * C1 + tid];
        cfB[tid] = g_coef[3 * C1 + tid];
    }
    if (tid < 64) b2s[tid] = b2[tid];
    if (tid < 128) {
        int q = q0 + (tid >> 5);
        int s = g_nbr[q * KK + (tid & 31)];
        es2[tid] = s;
        float rx = 0.f, ry = 0.f;
        if (s >= 0) {
            int d = g_pix[q];
            rx = pos[2 * s]     - pos[2 * d];
            ry = pos[2 * s + 1] - pos[2 * d + 1];
        }
        ex2[tid] = rx; ey2[tid] = ry;
    }
    __syncthreads();

    // h phase: channel = tid&127, edge half = tid>>7; edge-major tf32 store
    {
        int c = tid & 127;
        int e0 = (tid >> 7) * 64;
        float a = cfA[c], wx = cfX[c], wy = cfY[c], bb = cfB[c];
#pragma unroll 4
        for (int e = 0; e < 64; e++) {
            int ee = e0 + e;
            int s = es2[ee];
            float h = 0.f;
            if (s >= 0)
                h = fmaxf(fmaf(g_Y[s * C1 + c], a,
                          fmaf(ex2[ee], wx, fmaf(ey2[ee], wy, bb))), 0.f);
            hs[ee * HS + c] = __uint_as_float(f2tf32(h));
        }
    }
    __syncthreads();

    // mma phase
    int lane = tid & 31, w = tid >> 5;
    int g = lane >> 2, t = lane & 3;
    int ng = w & 3, mg = w >> 2;
    int n0 = ng * 16;          // 16 output cols per warp (2 n-tiles)
    int e0 = mg * 64;          // 64 edges (2 queries) per warp-row-group

    // B fragments in registers: [kstep][ntile][2]
    unsigned bf[16][2][2];
#pragma unroll
    for (int k = 0; k < 16; k++)
#pragma unroll
        for (int nt = 0; nt < 2; nt++) {
            bf[k][nt][0] = f2tf32(W2s[(k * 8 + t)     * WS + n0 + nt * 8 + g]);
            bf[k][nt][1] = f2tf32(W2s[(k * 8 + t + 4) * WS + n0 + nt * 8 + g]);
        }

#pragma unroll
    for (int qq = 0; qq < 2; qq++) {
        float rm[2][2] = {{NI, NI}, {NI, NI}};
        int qloc = mg * 2 + qq;
#pragma unroll
        for (int mt = 0; mt < 2; mt++) {
            int eb = e0 + qq * 32 + mt * 16;
            float d[2][4] = {{0.f,0.f,0.f,0.f},{0.f,0.f,0.f,0.f}};
#pragma unroll
            for (int k = 0; k < 16; k++) {
                const float* hp = hs + (eb + g) * HS + k * 8 + t;
                unsigned a0 = __float_as_uint(hp[0]);
                unsigned a2 = __float_as_uint(hp[4]);
                unsigned a1 = __float_as_uint(hp[8 * HS]);
                unsigned a3 = __float_as_uint(hp[8 * HS + 4]);
#pragma unroll
                for (int nt = 0; nt < 2; nt++) {
                    asm volatile(
                        "mma.sync.aligned.m16n8k8.row.col.f32.tf32.tf32.f32 "
                        "{%0,%1,%2,%3}, {%4,%5,%6,%7}, {%8,%9}, {%0,%1,%2,%3};"
                        : "+f"(d[nt][0]), "+f"(d[nt][1]), "+f"(d[nt][2]), "+f"(d[nt][3])
                        : "r"(a0), "r"(a1), "r"(a2), "r"(a3),
                          "r"(bf[k][nt][0]), "r"(bf[k][nt][1]));
                }
            }
            bool vlo = es2[eb + g] >= 0;
            bool vhi = es2[eb + 8 + g] >= 0;
#pragma unroll
            for (int nt = 0; nt < 2; nt++) {
                float x0 = vlo ? d[nt][0] : NI, x2 = vhi ? d[nt][2] : NI;
                float x1 = vlo ? d[nt][1] : NI, x3 = vhi ? d[nt][3] : NI;
                rm[nt][0] = fmaxf(rm[nt][0], fmaxf(x0, x2));
                rm[nt][1] = fmaxf(rm[nt][1], fmaxf(x1, x3));
            }
        }
        // reduce over g (lanes xor 4,8,16) -> column max over all 32 edges
#pragma unroll
        for (int nt = 0; nt < 2; nt++)
#pragma unroll
            for (int j = 0; j < 2; j++) {
                float v = rm[nt][j];
                v = fmaxf(v, __shfl_xor_sync(0xffffffffu, v, 4));
                v = fmaxf(v, __shfl_xor_sync(0xffffffffu, v, 8));
                v = fmaxf(v, __shfl_xor_sync(0xffffffffu, v, 16));
                rm[nt][j] = v;
            }
        if (lane < 4) {
#pragma unroll
            for (int nt = 0; nt < 2; nt++) {
                qmx[qloc * 64 + n0 + nt * 8 + 2 * t]     = rm[nt][0];
                qmx[qloc * 64 + n0 + nt * 8 + 2 * t + 1] = rm[nt][1];
            }
        }
    }
    __syncthreads();

    // global fold: one atomic per (query, channel)
    {
        float v = qmx[tid];
        if (__float_as_uint(v) != 0xff800000u) {
            int col = tid & 63, qloc = tid >> 6;
            int q = q0 + qloc;
            int P = g_pix[q];
            atomicMax(&out_u[(P >> 10) * (FF * PP) + col * PP + (P & 1023)],
                      encf(v + b2s[col]));
        }
    }
}

// ---------------- kernel 6: self-loop messages (target = own node) ---------
__global__ void k_self(const float* __restrict__ W2, const float* __restrict__ b2,
                       unsigned* __restrict__ out_u) {
    extern __shared__ float sm[];
    float* W2s = sm;
    float* hsl = sm + 8192;
    float* cfA = hsl + 128 * HSTR2;
    float* cfB = cfA + 128;
    float* b2s = cfB + 128;

    int tid = threadIdx.x;
    int i0 = blockIdx.x * 64;

    for (int i = tid; i < 8192; i += 128) W2s[i] = W2[i];
    cfA[tid] = g_coef[tid];
    cfB[tid] = g_coef[3 * C1 + tid];
    if (tid < 64) b2s[tid] = b2[tid];
    __syncthreads();

    {
        float a = cfA[tid], bb = cfB[tid];
#pragma unroll 4
        for (int e = 0; e < 64; e++)
            hsl[tid * HSTR2 + e] = fmaxf(fmaf(g_Y[(i0 + e) * C1 + tid], a, bb), 0.f);
    }
    __syncthreads();

    int eg = tid & 15, fg = tid >> 4;
    float acc[4][8];
#pragma unroll
    for (int e = 0; e < 4; e++)
#pragma unroll
        for (int f = 0; f < 8; f++) acc[e][f] = 0.f;

    const float* hb = hsl + eg * 4;
    const float* wb = W2s + fg * 8;
    for (int c = 0; c < C1; c++) {
        float4 hv = *(const float4*)(hb + c * HSTR2);
        float4 w0 = *(const float4*)(wb + c * 64);
        float4 w1 = *(const float4*)(wb + c * 64 + 4);
        float hvv[4] = {hv.x, hv.y, hv.z, hv.w};
        float wv[8]  = {w0.x, w0.y, w0.z, w0.w, w1.x, w1.y, w1.z, w1.w};
#pragma unroll
        for (int e = 0; e < 4; e++)
#pragma unroll
            for (int f = 0; f < 8; f++)
                acc[e][f] = fmaf(hvv[e], wv[f], acc[e][f]);
    }

#pragma unroll
    for (int e = 0; e < 4; e++) {
        int node = i0 + eg * 4 + e;
        unsigned base = (unsigned)((node >> 10) * (FF * PP) + (node & 1023));
#pragma unroll
        for (int f = 0; f < 8; f++) {
            float v = acc[e][f] + b2s[fg * 8 + f];
            atomicMax(&out_u[base + (fg * 8 + f) * PP], encf(v));
        }
    }
}

// ---------------- kernel 7: decode in place ----------------
__global__ void k_decode(unsigned* __restrict__ out_u) {
    int i = blockIdx.x * 256 + threadIdx.x;
    if (i < NPTS * FF) {
        unsigned u = out_u[i];
        ((float*)out_u)[i] = decf(u);
    }
}

// ---------------- launch ----------------
extern "C" void kernel_launch(void* const* d_in, const int* in_sizes, int n_in,
                              void* d_out, int out_size) {
    const float* x      = (const float*)d_in[0];
    const float* pos    = (const float*)d_in[1];
    const int*   batch  = (const int*)  d_in[2];
    const float* W1     = (const float*)d_in[3];
    const float* b1     = (const float*)d_in[4];
    const float* gamma1 = (const float*)d_in[5];
    const float* beta1  = (const float*)d_in[6];
    const float* W2     = (const float*)d_in[7];
    const float* b2     = (const float*)d_in[8];
    unsigned* out_u = (unsigned*)d_out;

    cudaFuncSetAttribute(k_main, cudaFuncAttributeMaxDynamicSharedMemorySize, SMEM_MAIN_BYTES);
    cudaFuncSetAttribute(k_self, cudaFuncAttributeMaxDynamicSharedMemorySize, SMEM_SELF_BYTES);

    k_init  <<<(NPTS * FF + 255) / 256, 256>>>(out_u);
    k_pre   <<<NPTS / 64, 256>>>(x, pos, batch, W1);
    k_nbr   <<<NB * 4, 256>>>(pos);
    k_stats <<<STATB, 256>>>(pos, W1, b1);
    k_reduce<<<1, 128>>>(W1, b1, gamma1, beta1);
    k_main  <<<NPTS / 4, 256, SMEM_MAIN_BYTES>>>(pos, W2, b2, out_u);
    k_self  <<<NPTS / 64, 128, SMEM_SELF_BYTES>>>(W2, b2, out_u);
    k_decode<<<(NPTS * FF + 255) / 256, 256>>>(out_u);
}

// round 8
// speedup vs baseline: 1.8747x; 1.7375x over previous
#include <cuda_runtime.h>

// ---------------- problem constants ----------------
#define NPTS   32768        // B*P
#define PP     1024         // points per sample
#define NB     32           // batch
#define FF     64           // feature dim
#define KK     32           // max neighbors
#define C1     128          // hidden dim
#define STATB  1024         // stat blocks (32 queries each, 8 partials per block)
#define NSLOT  (8 * STATB)
#define ENC_NEG_INF 0x007FFFFFu
#define CAP    128          // candidate cap in k_nbr (P(overflow) ~ 0)

#define HS 132              // h smem stride (edge-major)
#define WS 72               // W2 smem stride
#define SMEM_MAIN_FLOATS (128*HS + 128*WS + 4*C1 + 64 + 128 + 128 + 128 + 256)
#define SMEM_MAIN_BYTES  (SMEM_MAIN_FLOATS * 4)

#define HSTR2 72
#define SMEM_SELF_FLOATS (8192 + 128*HSTR2 + 128 + 128 + 64)
#define SMEM_SELF_BYTES  (SMEM_SELF_FLOATS * 4)

// ---------------- device scratch (static, no allocation) ----------------
__device__ float    g_Y[NPTS * C1];         // x @ W1[:64]  (16 MB)
__device__ int      g_pix[NPTS];
__device__ int      g_nbr[NPTS * KK];
__device__ float    g_psum[NSLOT * C1];
__device__ float    g_psq [NSLOT * C1];
__device__ int      g_pcnt[NSLOT];
__device__ float    g_coef[4 * C1];         // alpha | w64*a | w65*a | beta+(b1-mean)*a

__device__ __forceinline__ unsigned encf(float f) {
    unsigned u = __float_as_uint(f);
    return (u & 0x80000000u) ? ~u : (u | 0x80000000u);
}
__device__ __forceinline__ float decf(unsigned u) {
    return (u & 0x80000000u) ? __uint_as_float(u & 0x7fffffffu)
                             : __uint_as_float(~u);
}
__device__ __forceinline__ unsigned f2tf32(float f) {
    unsigned u;
    asm("cvt.rna.tf32.f32 %0, %1;" : "=r"(u) : "f"(f));
    return u;
}

// depth-5 tree argmax over best[32] (fully unrolled -> registers)
__device__ __forceinline__ void tree_max32(const float* best, float& bmax, int& bpos) {
    float m16[16]; int i16[16];
#pragma unroll
    for (int k = 0; k < 16; k++) {
        bool p = best[2*k] >= best[2*k+1];
        m16[k] = p ? best[2*k] : best[2*k+1];
        i16[k] = p ? 2*k : 2*k+1;
    }
    float m8[8]; int i8[8];
#pragma unroll
    for (int k = 0; k < 8; k++) {
        bool p = m16[2*k] >= m16[2*k+1];
        m8[k] = p ? m16[2*k] : m16[2*k+1];
        i8[k] = p ? i16[2*k] : i16[2*k+1];
    }
    float m4[4]; int i4[4];
#pragma unroll
    for (int k = 0; k < 4; k++) {
        bool p = m8[2*k] >= m8[2*k+1];
        m4[k] = p ? m8[2*k] : m8[2*k+1];
        i4[k] = p ? i8[2*k] : i8[2*k+1];
    }
    float m2[2]; int i2[2];
#pragma unroll
    for (int k = 0; k < 2; k++) {
        bool p = m4[2*k] >= m4[2*k+1];
        m2[k] = p ? m4[2*k] : m4[2*k+1];
        i2[k] = p ? i4[2*k] : i4[2*k+1];
    }
    bool p = m2[0] >= m2[1];
    bmax = p ? m2[0] : m2[1];
    bpos = p ? i2[0] : i2[1];
}

// ---------------- kernel 0: init output accumulator ----------------
__global__ void k_init(unsigned* __restrict__ out_u) {
    int i = blockIdx.x * 256 + threadIdx.x;
    if (i < NPTS * FF) out_u[i] = ENC_NEG_INF;
}

// ---------------- kernel 1: pixel index + Y = x @ W1[:64] ----------------
__global__ void k_pre(const float* __restrict__ x, const float* __restrict__ pos,
                      const int* __restrict__ batch, const float* __restrict__ W1) {
    __shared__ float w1s[64 * C1];
    __shared__ float xs[64 * FF];
    int tid = threadIdx.x;
    int p0 = blockIdx.x * 64;

    for (int i = tid; i < 64 * C1; i += 256) w1s[i] = W1[i];
    for (int i = tid; i < 64 * FF; i += 256) xs[i] = x[p0 * FF + i];
    if (tid < 64) {
        int i = p0 + tid;
        float px = pos[2 * i], py = pos[2 * i + 1];
        int col = (int)(px * 32.0f); col = min(max(col, 0), 31);
        int row = (int)(py * 32.0f); row = min(max(row, 0), 31);
        g_pix[i] = batch[i] * (NB * NB) + row * 32 + col;
    }
    __syncthreads();

    int pg = tid >> 5;
    int c0 = (tid & 31) * 4;
    float acc[8][4];
#pragma unroll
    for (int p = 0; p < 8; p++)
#pragma unroll
        for (int c = 0; c < 4; c++) acc[p][c] = 0.f;

    for (int r = 0; r < 64; r++) {
        float4 w = *(const float4*)&w1s[r * C1 + c0];
#pragma unroll
        for (int p = 0; p < 8; p++) {
            float xv = xs[(pg * 8 + p) * FF + r];
            acc[p][0] = fmaf(xv, w.x, acc[p][0]);
            acc[p][1] = fmaf(xv, w.y, acc[p][1]);
            acc[p][2] = fmaf(xv, w.z, acc[p][2]);
            acc[p][3] = fmaf(xv, w.w, acc[p][3]);
        }
    }
#pragma unroll
    for (int p = 0; p < 8; p++) {
        int pt = p0 + pg * 8 + p;
        *(float4*)&g_Y[pt * C1 + c0] =
            make_float4(acc[p][0], acc[p][1], acc[p][2], acc[p][3]);
    }
}

// ---------------- kernel 2: radius ball-query, K nearest (compact) --------
__global__ void k_nbr(const float* __restrict__ pos) {
    __shared__ float2 ps[PP];
    int tid = threadIdx.x;
    int b = blockIdx.x >> 2;
    const float2* pb = (const float2*)pos + b * PP;
    for (int i = tid; i < PP; i += 256) ps[i] = pb[i];
    __syncthreads();

    int ql = ((blockIdx.x & 3) << 8) + tid;
    int q = b * PP + ql;
    float qx = ps[ql].x, qy = ps[ql].y;
    const float R2 = 0.01f;
    const float INF = __int_as_float(0x7f800000);
    int pixq = g_pix[q];

    // pass 1: compact in-ball candidates to local arrays (ascending j order)
    float cd2[CAP];
    int   cj [CAP];
    int c = 0;
    for (int j = 0; j < PP; j++) {
        float dx = __fsub_rn(qx, ps[j].x);
        float dy = __fsub_rn(qy, ps[j].y);
        float d2 = __fadd_rn(__fmul_rn(dx, dx), __fmul_rn(dy, dy));
        if (d2 <= R2) {
            if (c < CAP) { cd2[c] = d2; cj[c] = j; }
            c++;
        }
    }

    if (c <= CAP) {
        float t = INF;
        int quota = 0;
        bool need_sel = (c > KK);
        if (need_sel) {
            float best[32];
#pragma unroll
            for (int k = 0; k < 32; k++) best[k] = cd2[k];
            float bmax; int bpos;
            tree_max32(best, bmax, bpos);
            for (int i = 32; i < c; i++) {
                float d = cd2[i];
                if (d < bmax) {
#pragma unroll
                    for (int k = 0; k < 32; k++) best[k] = (k == bpos) ? d : best[k];
                    tree_max32(best, bmax, bpos);
                }
            }
            t = bmax;
            int c1 = 0;
            for (int i = 0; i < c; i++) c1 += (cd2[i] < t) ? 1 : 0;
            quota = KK - c1;
        }
        int kout = 0;
        for (int i = 0; i < c; i++) {
            bool take;
            if (!need_sel) take = true;
            else {
                float d = cd2[i];
                if (d < t) take = true;
                else if (d == t && quota > 0) { take = true; quota--; }
                else take = false;
            }
            if (take) {
                int s = b * PP + cj[i];
                if (s != pixq) g_nbr[q * KK + (kout++)] = s;
            }
        }
        for (; kout < KK; kout++) g_nbr[q * KK + kout] = -1;
    } else {
        // overflow fallback (never expected): full streaming selection
        float best[32];
#pragma unroll
        for (int k = 0; k < 32; k++) best[k] = INF;
        float bmax = INF; int bpos = 0;
        for (int j = 0; j < PP; j++) {
            float dx = __fsub_rn(qx, ps[j].x);
            float dy = __fsub_rn(qy, ps[j].y);
            float d2 = __fadd_rn(__fmul_rn(dx, dx), __fmul_rn(dy, dy));
            if (d2 <= R2 && d2 < bmax) {
#pragma unroll
                for (int k = 0; k < 32; k++) best[k] = (k == bpos) ? d2 : best[k];
                tree_max32(best, bmax, bpos);
            }
        }
        float t = bmax;
        int c1 = 0;
        for (int j = 0; j < PP; j++) {
            float dx = __fsub_rn(qx, ps[j].x);
            float dy = __fsub_rn(qy, ps[j].y);
            float d2 = __fadd_rn(__fmul_rn(dx, dx), __fmul_rn(dy, dy));
            c1 += (d2 <= R2 && d2 < t) ? 1 : 0;
        }
        int quota = KK - c1;
        int kout = 0;
        for (int j = 0; j < PP; j++) {
            float dx = __fsub_rn(qx, ps[j].x);
            float dy = __fsub_rn(qy, ps[j].y);
            float d2 = __fadd_rn(__fmul_rn(dx, dx), __fmul_rn(dy, dy));
            if (d2 > R2) continue;
            bool take = false;
            if (d2 < t) take = true;
            else if (d2 == t && quota > 0) { take = true; quota--; }
            if (take) {
                int s = b * PP + j;
                if (s != pixq) g_nbr[q * KK + (kout++)] = s;
            }
        }
        for (; kout < KK; kout++) g_nbr[q * KK + kout] = -1;
    }
}

// ---------------- kernel 3: BN partial stats (float4, 8 partials/block) ----
__global__ void k_stats(const float* __restrict__ pos, const float* __restrict__ W1,
                        const float* __restrict__ b1) {
    __shared__ int   es[1056];
    __shared__ float ex[1056];
    __shared__ float ey[1056];
    int tid = threadIdx.x;
    int q0 = blockIdx.x * 32;

    for (int idx = tid; idx < 1024; idx += 256) {
        int q = q0 + (idx >> 5);
        int s = g_nbr[q * KK + (idx & 31)];
        es[idx] = s;
        float rx = 0.f, ry = 0.f;
        if (s >= 0) {
            int d = g_pix[q];
            rx = pos[2 * s]     - pos[2 * d];
            ry = pos[2 * s + 1] - pos[2 * d + 1];
        }
        ex[idx] = rx; ey[idx] = ry;
    }
    if (tid < 32) { es[1024 + tid] = q0 + tid; ex[1024 + tid] = 0.f; ey[1024 + tid] = 0.f; }
    __syncthreads();

    int c0 = (tid & 31) * 4;
    int part = tid >> 5;            // 0..7, each covers 132 edge slots
    float4 w64 = *(const float4*)&W1[64 * C1 + c0];
    float4 w65 = *(const float4*)&W1[65 * C1 + c0];
    float4 b1v = *(const float4*)&b1[c0];
    float4 sum = make_float4(0.f, 0.f, 0.f, 0.f);
    float4 sq  = make_float4(0.f, 0.f, 0.f, 0.f);
    int cnt = 0;
    int e0 = part * 132;
#pragma unroll 4
    for (int e = e0; e < e0 + 132; e++) {
        int s = es[e];
        if (s < 0) continue;
        cnt++;
        float4 y = *(const float4*)&g_Y[s * C1 + c0];
        float rx = ex[e], ry = ey[e];
        float z0 = fmaf(rx, w64.x, fmaf(ry, w65.x, y.x + b1v.x));
        float z1 = fmaf(rx, w64.y, fmaf(ry, w65.y, y.y + b1v.y));
        float z2 = fmaf(rx, w64.z, fmaf(ry, w65.z, y.z + b1v.z));
        float z3 = fmaf(rx, w64.w, fmaf(ry, w65.w, y.w + b1v.w));
        sum.x += z0; sum.y += z1; sum.z += z2; sum.w += z3;
        sq.x = fmaf(z0, z0, sq.x); sq.y = fmaf(z1, z1, sq.y);
        sq.z = fmaf(z2, z2, sq.z); sq.w = fmaf(z3, z3, sq.w);
    }
    int slot = blockIdx.x * 8 + part;
    *(float4*)&g_psum[slot * C1 + c0] = sum;
    *(float4*)&g_psq [slot * C1 + c0] = sq;
    if ((tid & 31) == 0) g_pcnt[slot] = cnt;
}

// ---------------- kernel 4: reduce stats -> fused BN coefficients ----------
// 16 blocks x 256 threads: one warp per channel.
__global__ void k_reduce(const float* __restrict__ W1, const float* __restrict__ b1,
                         const float* __restrict__ gamma1, const float* __restrict__ beta1) {
    int c = blockIdx.x * 8 + (threadIdx.x >> 5);
    int lane = threadIdx.x & 31;
    double s0 = 0.0, s1 = 0.0, q0 = 0.0, q1 = 0.0;
    long long cnt = 0;
    for (int i = lane; i < NSLOT; i += 64) {
        s0 += (double)g_psum[i * C1 + c];
        q0 += (double)g_psq [i * C1 + c];
        s1 += (double)g_psum[(i + 32) * C1 + c];
        q1 += (double)g_psq [(i + 32) * C1 + c];
        cnt += g_pcnt[i] + g_pcnt[i + 32];
    }
    double s = s0 + s1, sq = q0 + q1;
#pragma unroll
    for (int o = 16; o > 0; o >>= 1) {
        s   += __shfl_xor_sync(0xffffffffu, s, o);
        sq  += __shfl_xor_sync(0xffffffffu, sq, o);
        cnt += __shfl_xor_sync(0xffffffffu, cnt, o);
    }
    if (lane == 0) {
        double mean = s / (double)cnt;
        double var  = sq / (double)cnt - mean * mean;
        float A = gamma1[c] / sqrtf((float)var + 1e-5f);
        g_coef[c]           = A;
        g_coef[C1 + c]      = W1[64 * C1 + c] * A;
        g_coef[2 * C1 + c]  = W1[65 * C1 + c] * A;
        g_coef[3 * C1 + c]  = beta1[c] + (b1[c] - (float)mean) * A;
    }
}

// ---------------- kernel 5: main fused (h -> tf32 mma -> max scatter) ------
// 8192 blocks x 256 threads; 4 queries (128 edge slots) per block.
// k-outermost mma loop, B re-read from smem each step -> no register spills.
__global__ void __launch_bounds__(256, 2)
k_main(const float* __restrict__ pos, const float* __restrict__ W2,
       const float* __restrict__ b2, unsigned* __restrict__ out_u) {
    extern __shared__ float sm[];
    float* hs  = sm;                        // tf32 bits, edge-major [128][HS]
    float* W2s = sm + 128 * HS;             // tf32 bits [128][WS]
    float* cfA = W2s + 128 * WS;
    float* cfX = cfA + C1;
    float* cfY = cfX + C1;
    float* cfB = cfY + C1;
    float* b2s = cfB + C1;
    float* ex2 = b2s + 64;
    float* ey2 = ex2 + 128;
    int*   es2 = (int*)(ey2 + 128);
    float* qmx = (float*)(es2 + 128);       // [4 queries][64 cols]

    int tid = threadIdx.x;
    int q0 = blockIdx.x * 4;
    const float NI = __int_as_float(0xff800000);

    for (int i = tid; i < 8192; i += 256)
        W2s[(i >> 6) * WS + (i & 63)] = __uint_as_float(f2tf32(W2[i]));
    if (tid < 128) {
        cfA[tid] = g_coef[tid];
        cfX[tid] = g_coef[C1 + tid];
        cfY[tid] = g_coef[2 * C1 + tid];
        cfB[tid] = g_coef[3 * C1 + tid];
    }
    if (tid < 64) b2s[tid] = b2[tid];
    if (tid < 128) {
        int q = q0 + (tid >> 5);
        int s = g_nbr[q * KK + (tid & 31)];
        es2[tid] = s;
        float rx = 0.f, ry = 0.f;
        if (s >= 0) {
            int d = g_pix[q];
            rx = pos[2 * s]     - pos[2 * d];
            ry = pos[2 * s + 1] - pos[2 * d + 1];
        }
        ex2[tid] = rx; ey2[tid] = ry;
    }
    __syncthreads();

    // h phase: channel = tid&127, edge half = tid>>7; edge-major tf32 store
    {
        int c = tid & 127;
        int e0h = (tid >> 7) * 64;
        float a = cfA[c], wx = cfX[c], wy = cfY[c], bb = cfB[c];
#pragma unroll 8
        for (int e = 0; e < 64; e++) {
            int ee = e0h + e;
            int s = es2[ee];
            float h = 0.f;
            if (s >= 0)
                h = fmaxf(fmaf(g_Y[s * C1 + c], a,
                          fmaf(ex2[ee], wx, fmaf(ey2[ee], wy, bb))), 0.f);
            hs[ee * HS + c] = __uint_as_float(f2tf32(h));
        }
    }
    __syncthreads();

    // mma phase: warp handles 64 edges (2 queries) x 16 cols; k outermost
    int lane = tid & 31, w = tid >> 5;
    int g = lane >> 2, t = lane & 3;
    int ng = w & 3, mg = w >> 2;
    int n0 = ng * 16;
    int e0 = mg * 64;

    float d[2][2][2][4];                 // [qq][mt][nt][4]
#pragma unroll
    for (int a1 = 0; a1 < 2; a1++)
#pragma unroll
        for (int a2 = 0; a2 < 2; a2++)
#pragma unroll
            for (int a3 = 0; a3 < 2; a3++)
#pragma unroll
                for (int a4 = 0; a4 < 4; a4++) d[a1][a2][a3][a4] = 0.f;

#pragma unroll
    for (int k = 0; k < 16; k++) {
        const float* wrow0 = W2s + (k * 8 + t) * WS + n0 + g;
        const float* wrow1 = W2s + (k * 8 + t + 4) * WS + n0 + g;
        unsigned b00 = __float_as_uint(wrow0[0]);
        unsigned b01 = __float_as_uint(wrow1[0]);
        unsigned b10 = __float_as_uint(wrow0[8]);
        unsigned b11 = __float_as_uint(wrow1[8]);
#pragma unroll
        for (int qq = 0; qq < 2; qq++)
#pragma unroll
            for (int mt = 0; mt < 2; mt++) {
                const float* hp = hs + (e0 + qq * 32 + mt * 16 + g) * HS + k * 8 + t;
                unsigned a0 = __float_as_uint(hp[0]);
                unsigned a2 = __float_as_uint(hp[4]);
                unsigned a1 = __float_as_uint(hp[8 * HS]);
                unsigned a3 = __float_as_uint(hp[8 * HS + 4]);
                asm volatile(
                    "mma.sync.aligned.m16n8k8.row.col.f32.tf32.tf32.f32 "
                    "{%0,%1,%2,%3}, {%4,%5,%6,%7}, {%8,%9}, {%0,%1,%2,%3};"
                    : "+f"(d[qq][mt][0][0]), "+f"(d[qq][mt][0][1]),
                      "+f"(d[qq][mt][0][2]), "+f"(d[qq][mt][0][3])
                    : "r"(a0), "r"(a1), "r"(a2), "r"(a3), "r"(b00), "r"(b01));
                asm volatile(
                    "mma.sync.aligned.m16n8k8.row.col.f32.tf32.tf32.f32 "
                    "{%0,%1,%2,%3}, {%4,%5,%6,%7}, {%8,%9}, {%0,%1,%2,%3};"
                    : "+f"(d[qq][mt][1][0]), "+f"(d[qq][mt][1][1]),
                      "+f"(d[qq][mt][1][2]), "+f"(d[qq][mt][1][3])
                    : "r"(a0), "r"(a1), "r"(a2), "r"(a3), "r"(b10), "r"(b11));
            }
    }

#pragma unroll
    for (int qq = 0; qq < 2; qq++) {
        float rm[2][2] = {{NI, NI}, {NI, NI}};
        int qloc = mg * 2 + qq;
#pragma unroll
        for (int mt = 0; mt < 2; mt++) {
            int eb = e0 + qq * 32 + mt * 16;
            bool vlo = es2[eb + g] >= 0;
            bool vhi = es2[eb + 8 + g] >= 0;
#pragma unroll
            for (int nt = 0; nt < 2; nt++) {
                float x0 = vlo ? d[qq][mt][nt][0] : NI;
                float x1 = vlo ? d[qq][mt][nt][1] : NI;
                float x2 = vhi ? d[qq][mt][nt][2] : NI;
                float x3 = vhi ? d[qq][mt][nt][3] : NI;
                rm[nt][0] = fmaxf(rm[nt][0], fmaxf(x0, x2));
                rm[nt][1] = fmaxf(rm[nt][1], fmaxf(x1, x3));
            }
        }
#pragma unroll
        for (int nt = 0; nt < 2; nt++)
#pragma unroll
            for (int j = 0; j < 2; j++) {
                float v = rm[nt][j];
                v = fmaxf(v, __shfl_xor_sync(0xffffffffu, v, 4));
                v = fmaxf(v, __shfl_xor_sync(0xffffffffu, v, 8));
                v = fmaxf(v, __shfl_xor_sync(0xffffffffu, v, 16));
                rm[nt][j] = v;
            }
        if (lane < 4) {
#pragma unroll
            for (int nt = 0; nt < 2; nt++) {
                qmx[qloc * 64 + n0 + nt * 8 + 2 * t]     = rm[nt][0];
                qmx[qloc * 64 + n0 + nt * 8 + 2 * t + 1] = rm[nt][1];
            }
        }
    }
    __syncthreads();

    {
        float v = qmx[tid];
        if (__float_as_uint(v) != 0xff800000u) {
            int col = tid & 63, qloc = tid >> 6;
            int q = q0 + qloc;
            int P = g_pix[q];
            atomicMax(&out_u[(P >> 10) * (FF * PP) + col * PP + (P & 1023)],
                      encf(v + b2s[col]));
        }
    }
}

// ---------------- kernel 6: self-loop messages (target = own node) ---------
__global__ void k_self(const float* __restrict__ W2, const float* __restrict__ b2,
                       unsigned* __restrict__ out_u) {
    extern __shared__ float sm[];
    float* W2s = sm;
    float* hsl = sm + 8192;
    float* cfA = hsl + 128 * HSTR2;
    float* cfB = cfA + 128;
    float* b2s = cfB + 128;

    int tid = threadIdx.x;
    int i0 = blockIdx.x * 64;

    for (int i = tid; i < 8192; i += 128) W2s[i] = W2[i];
    cfA[tid] = g_coef[tid];
    cfB[tid] = g_coef[3 * C1 + tid];
    if (tid < 64) b2s[tid] = b2[tid];
    __syncthreads();

    {
        float a = cfA[tid], bb = cfB[tid];
#pragma unroll 4
        for (int e = 0; e < 64; e++)
            hsl[tid * HSTR2 + e] = fmaxf(fmaf(g_Y[(i0 + e) * C1 + tid], a, bb), 0.f);
    }
    __syncthreads();

    int eg = tid & 15, fg = tid >> 4;
    float acc[4][8];
#pragma unroll
    for (int e = 0; e < 4; e++)
#pragma unroll
        for (int f = 0; f < 8; f++) acc[e][f] = 0.f;

    const float* hb = hsl + eg * 4;
    const float* wb = W2s + fg * 8;
    for (int c = 0; c < C1; c++) {
        float4 hv = *(const float4*)(hb + c * HSTR2);
        float4 w0 = *(const float4*)(wb + c * 64);
        float4 w1 = *(const float4*)(wb + c * 64 + 4);
        float hvv[4] = {hv.x, hv.y, hv.z, hv.w};
        float wv[8]  = {w0.x, w0.y, w0.z, w0.w, w1.x, w1.y, w1.z, w1.w};
#pragma unroll
        for (int e = 0; e < 4; e++)
#pragma unroll
            for (int f = 0; f < 8; f++)
                acc[e][f] = fmaf(hvv[e], wv[f], acc[e][f]);
    }

#pragma unroll
    for (int e = 0; e < 4; e++) {
        int node = i0 + eg * 4 + e;
        unsigned base = (unsigned)((node >> 10) * (FF * PP) + (node & 1023));
#pragma unroll
        for (int f = 0; f < 8; f++) {
            float v = acc[e][f] + b2s[fg * 8 + f];
            atomicMax(&out_u[base + (fg * 8 + f) * PP], encf(v));
        }
    }
}

// ---------------- kernel 7: decode in place ----------------
__global__ void k_decode(unsigned* __restrict__ out_u) {
    int i = blockIdx.x * 256 + threadIdx.x;
    if (i < NPTS * FF) {
        unsigned u = out_u[i];
        ((float*)out_u)[i] = decf(u);
    }
}

// ---------------- launch ----------------
extern "C" void kernel_launch(void* const* d_in, const int* in_sizes, int n_in,
                              void* d_out, int out_size) {
    const float* x      = (const float*)d_in[0];
    const float* pos    = (const float*)d_in[1];
    const int*   batch  = (const int*)  d_in[2];
    const float* W1     = (const float*)d_in[3];
    const float* b1     = (const float*)d_in[4];
    const float* gamma1 = (const float*)d_in[5];
    const float* beta1  = (const float*)d_in[6];
    const float* W2     = (const float*)d_in[7];
    const float* b2     = (const float*)d_in[8];
    unsigned* out_u = (unsigned*)d_out;

    cudaFuncSetAttribute(k_main, cudaFuncAttributeMaxDynamicSharedMemorySize, SMEM_MAIN_BYTES);
    cudaFuncSetAttribute(k_self, cudaFuncAttributeMaxDynamicSharedMemorySize, SMEM_SELF_BYTES);

    k_init  <<<(NPTS * FF + 255) / 256, 256>>>(out_u);
    k_pre   <<<NPTS / 64, 256>>>(x, pos, batch, W1);
    k_nbr   <<<NB * 4, 256>>>(pos);
    k_stats <<<STATB, 256>>>(pos, W1, b1);
    k_reduce<<<16, 256>>>(W1, b1, gamma1, beta1);
    k_main  <<<NPTS / 4, 256, SMEM_MAIN_BYTES>>>(pos, W2, b2, out_u);
    k_self  <<<NPTS / 64, 128, SMEM_SELF_BYTES>>>(W2, b2, out_u);
    k_decode<<<(NPTS * FF + 255) / 256, 256>>>(out_u);
}

// round 9
// speedup vs baseline: 1.8763x; 1.0009x over previous
#include <cuda_runtime.h>

// ---------------- problem constants ----------------
#define NPTS   32768        // B*P
#define PP     1024         // points per sample
#define NB     32           // batch
#define FF     64           // feature dim
#define KK     32           // max neighbors
#define C1     128          // hidden dim
#define STATB  1024         // stat blocks (32 queries each, 8 partials per block)
#define NSLOT  (8 * STATB)
#define ENC_NEG_INF 0x007FFFFFu
#define CAP    128          // candidate cap in k_nbr (P(overflow) ~ 0)

#define HS 132              // h smem stride (edge-major)
#define WS 72               // W2 smem stride
#define SMEM_MAIN_FLOATS (128*HS + 128*WS + 4*C1 + 64 + 128 + 128 + 128 + 256)
#define SMEM_MAIN_BYTES  (SMEM_MAIN_FLOATS * 4)

#define HSTR2 72
#define SMEM_SELF_FLOATS (8192 + 128*HSTR2 + 128 + 128 + 64)
#define SMEM_SELF_BYTES  (SMEM_SELF_FLOATS * 4)

// ---------------- device scratch (static, no allocation) ----------------
__device__ float    g_Y[NPTS * C1];         // x @ W1[:64]  (16 MB)
__device__ int      g_pix[NPTS];
__device__ int      g_nbr[NPTS * KK];
__device__ float    g_psum[NSLOT * C1];
__device__ float    g_psq [NSLOT * C1];
__device__ int      g_pcnt[NSLOT];
__device__ float    g_coef[4 * C1];         // alpha | w64*a | w65*a | beta+(b1-mean)*a

__device__ __forceinline__ unsigned encf(float f) {
    unsigned u = __float_as_uint(f);
    return (u & 0x80000000u) ? ~u : (u | 0x80000000u);
}
__device__ __forceinline__ float decf(unsigned u) {
    return (u & 0x80000000u) ? __uint_as_float(u & 0x7fffffffu)
                             : __uint_as_float(~u);
}
__device__ __forceinline__ unsigned f2tf32(float f) {
    unsigned u;
    asm("cvt.rna.tf32.f32 %0, %1;" : "=r"(u) : "f"(f));
    return u;
}

// depth-5 tree argmax over best[32] (fully unrolled -> registers)
__device__ __forceinline__ void tree_max32(const float* best, float& bmax, int& bpos) {
    float m16[16]; int i16[16];
#pragma unroll
    for (int k = 0; k < 16; k++) {
        bool p = best[2*k] >= best[2*k+1];
        m16[k] = p ? best[2*k] : best[2*k+1];
        i16[k] = p ? 2*k : 2*k+1;
    }
    float m8[8]; int i8[8];
#pragma unroll
    for (int k = 0; k < 8; k++) {
        bool p = m16[2*k] >= m16[2*k+1];
        m8[k] = p ? m16[2*k] : m16[2*k+1];
        i8[k] = p ? i16[2*k] : i16[2*k+1];
    }
    float m4[4]; int i4[4];
#pragma unroll
    for (int k = 0; k < 4; k++) {
        bool p = m8[2*k] >= m8[2*k+1];
        m4[k] = p ? m8[2*k] : m8[2*k+1];
        i4[k] = p ? i8[2*k] : i8[2*k+1];
    }
    float m2[2]; int i2[2];
#pragma unroll
    for (int k = 0; k < 2; k++) {
        bool p = m4[2*k] >= m4[2*k+1];
        m2[k] = p ? m4[2*k] : m4[2*k+1];
        i2[k] = p ? i4[2*k] : i4[2*k+1];
    }
    bool p = m2[0] >= m2[1];
    bmax = p ? m2[0] : m2[1];
    bpos = p ? i2[0] : i2[1];
}

// ---------------- kernel 0: init output accumulator ----------------
__global__ void k_init(unsigned* __restrict__ out_u) {
    int i = blockIdx.x * 256 + threadIdx.x;
    if (i < NPTS * FF) out_u[i] = ENC_NEG_INF;
}

// ---------------- kernel 1: pixel index + Y = x @ W1[:64] ----------------
__global__ void k_pre(const float* __restrict__ x, const float* __restrict__ pos,
                      const int* __restrict__ batch, const float* __restrict__ W1) {
    __shared__ float w1s[64 * C1];
    __shared__ float xs[64 * FF];
    int tid = threadIdx.x;
    int p0 = blockIdx.x * 64;

    for (int i = tid; i < 64 * C1; i += 256) w1s[i] = W1[i];
    for (int i = tid; i < 64 * FF; i += 256) xs[i] = x[p0 * FF + i];
    if (tid < 64) {
        int i = p0 + tid;
        float px = pos[2 * i], py = pos[2 * i + 1];
        int col = (int)(px * 32.0f); col = min(max(col, 0), 31);
        int row = (int)(py * 32.0f); row = min(max(row, 0), 31);
        g_pix[i] = batch[i] * (NB * NB) + row * 32 + col;
    }
    __syncthreads();

    int pg = tid >> 5;
    int c0 = (tid & 31) * 4;
    float acc[8][4];
#pragma unroll
    for (int p = 0; p < 8; p++)
#pragma unroll
        for (int c = 0; c < 4; c++) acc[p][c] = 0.f;

    for (int r = 0; r < 64; r++) {
        float4 w = *(const float4*)&w1s[r * C1 + c0];
#pragma unroll
        for (int p = 0; p < 8; p++) {
            float xv = xs[(pg * 8 + p) * FF + r];
            acc[p][0] = fmaf(xv, w.x, acc[p][0]);
            acc[p][1] = fmaf(xv, w.y, acc[p][1]);
            acc[p][2] = fmaf(xv, w.z, acc[p][2]);
            acc[p][3] = fmaf(xv, w.w, acc[p][3]);
        }
    }
#pragma unroll
    for (int p = 0; p < 8; p++) {
        int pt = p0 + pg * 8 + p;
        *(float4*)&g_Y[pt * C1 + c0] =
            make_float4(acc[p][0], acc[p][1], acc[p][2], acc[p][3]);
    }
}

// ---------------- kernel 2: radius ball-query, K nearest (compact) --------
__global__ void k_nbr(const float* __restrict__ pos) {
    __shared__ float2 ps[PP];
    int tid = threadIdx.x;
    int b = blockIdx.x >> 2;
    const float2* pb = (const float2*)pos + b * PP;
    for (int i = tid; i < PP; i += 256) ps[i] = pb[i];
    __syncthreads();

    int ql = ((blockIdx.x & 3) << 8) + tid;
    int q = b * PP + ql;
    float qx = ps[ql].x, qy = ps[ql].y;
    const float R2 = 0.01f;
    const float INF = __int_as_float(0x7f800000);
    int pixq = g_pix[q];

    // pass 1: compact in-ball candidates to local arrays (ascending j order)
    float cd2[CAP];
    int   cj [CAP];
    int c = 0;
    for (int j = 0; j < PP; j++) {
        float dx = __fsub_rn(qx, ps[j].x);
        float dy = __fsub_rn(qy, ps[j].y);
        float d2 = __fadd_rn(__fmul_rn(dx, dx), __fmul_rn(dy, dy));
        if (d2 <= R2) {
            if (c < CAP) { cd2[c] = d2; cj[c] = j; }
            c++;
        }
    }

    if (c <= CAP) {
        float t = INF;
        int quota = 0;
        bool need_sel = (c > KK);
        if (need_sel) {
            float best[32];
#pragma unroll
            for (int k = 0; k < 32; k++) best[k] = cd2[k];
            float bmax; int bpos;
            tree_max32(best, bmax, bpos);
            for (int i = 32; i < c; i++) {
                float d = cd2[i];
                if (d < bmax) {
#pragma unroll
                    for (int k = 0; k < 32; k++) best[k] = (k == bpos) ? d : best[k];
                    tree_max32(best, bmax, bpos);
                }
            }
            t = bmax;
            int c1 = 0;
            for (int i = 0; i < c; i++) c1 += (cd2[i] < t) ? 1 : 0;
            quota = KK - c1;
        }
        int kout = 0;
        for (int i = 0; i < c; i++) {
            bool take;
            if (!need_sel) take = true;
            else {
                float d = cd2[i];
                if (d < t) take = true;
                else if (d == t && quota > 0) { take = true; quota--; }
                else take = false;
            }
            if (take) {
                int s = b * PP + cj[i];
                if (s != pixq) g_nbr[q * KK + (kout++)] = s;
            }
        }
        for (; kout < KK; kout++) g_nbr[q * KK + kout] = -1;
    } else {
        // overflow fallback (never expected): full streaming selection
        float best[32];
#pragma unroll
        for (int k = 0; k < 32; k++) best[k] = INF;
        float bmax = INF; int bpos = 0;
        for (int j = 0; j < PP; j++) {
            float dx = __fsub_rn(qx, ps[j].x);
            float dy = __fsub_rn(qy, ps[j].y);
            float d2 = __fadd_rn(__fmul_rn(dx, dx), __fmul_rn(dy, dy));
            if (d2 <= R2 && d2 < bmax) {
#pragma unroll
                for (int k = 0; k < 32; k++) best[k] = (k == bpos) ? d2 : best[k];
                tree_max32(best, bmax, bpos);
            }
        }
        float t = bmax;
        int c1 = 0;
        for (int j = 0; j < PP; j++) {
            float dx = __fsub_rn(qx, ps[j].x);
            float dy = __fsub_rn(qy, ps[j].y);
            float d2 = __fadd_rn(__fmul_rn(dx, dx), __fmul_rn(dy, dy));
            c1 += (d2 <= R2 && d2 < t) ? 1 : 0;
        }
        int quota = KK - c1;
        int kout = 0;
        for (int j = 0; j < PP; j++) {
            float dx = __fsub_rn(qx, ps[j].x);
            float dy = __fsub_rn(qy, ps[j].y);
            float d2 = __fadd_rn(__fmul_rn(dx, dx), __fmul_rn(dy, dy));
            if (d2 > R2) continue;
            bool take = false;
            if (d2 < t) take = true;
            else if (d2 == t && quota > 0) { take = true; quota--; }
            if (take) {
                int s = b * PP + j;
                if (s != pixq) g_nbr[q * KK + (kout++)] = s;
            }
        }
        for (; kout < KK; kout++) g_nbr[q * KK + kout] = -1;
    }
}

// ---------------- kernel 3: BN partial stats (float4, 8 partials/block) ----
__global__ void k_stats(const float* __restrict__ pos, const float* __restrict__ W1,
                        const float* __restrict__ b1) {
    __shared__ int   es[1056];
    __shared__ float ex[1056];
    __shared__ float ey[1056];
    int tid = threadIdx.x;
    int q0 = blockIdx.x * 32;

    for (int idx = tid; idx < 1024; idx += 256) {
        int q = q0 + (idx >> 5);
        int s = g_nbr[q * KK + (idx & 31)];
        es[idx] = s;
        float rx = 0.f, ry = 0.f;
        if (s >= 0) {
            int d = g_pix[q];
            rx = pos[2 * s]     - pos[2 * d];
            ry = pos[2 * s + 1] - pos[2 * d + 1];
        }
        ex[idx] = rx; ey[idx] = ry;
    }
    if (tid < 32) { es[1024 + tid] = q0 + tid; ex[1024 + tid] = 0.f; ey[1024 + tid] = 0.f; }
    __syncthreads();

    int c0 = (tid & 31) * 4;
    int part = tid >> 5;            // 0..7, each covers 132 edge slots
    float4 w64 = *(const float4*)&W1[64 * C1 + c0];
    float4 w65 = *(const float4*)&W1[65 * C1 + c0];
    float4 b1v = *(const float4*)&b1[c0];
    float4 sum = make_float4(0.f, 0.f, 0.f, 0.f);
    float4 sq  = make_float4(0.f, 0.f, 0.f, 0.f);
    int cnt = 0;
    int e0 = part * 132;
#pragma unroll 4
    for (int e = e0; e < e0 + 132; e++) {
        int s = es[e];
        if (s < 0) continue;
        cnt++;
        float4 y = *(const float4*)&g_Y[s * C1 + c0];
        float rx = ex[e], ry = ey[e];
        float z0 = fmaf(rx, w64.x, fmaf(ry, w65.x, y.x + b1v.x));
        float z1 = fmaf(rx, w64.y, fmaf(ry, w65.y, y.y + b1v.y));
        float z2 = fmaf(rx, w64.z, fmaf(ry, w65.z, y.z + b1v.z));
        float z3 = fmaf(rx, w64.w, fmaf(ry, w65.w, y.w + b1v.w));
        sum.x += z0; sum.y += z1; sum.z += z2; sum.w += z3;
        sq.x = fmaf(z0, z0, sq.x); sq.y = fmaf(z1, z1, sq.y);
        sq.z = fmaf(z2, z2, sq.z); sq.w = fmaf(z3, z3, sq.w);
    }
    int slot = blockIdx.x * 8 + part;
    *(float4*)&g_psum[slot * C1 + c0] = sum;
    *(float4*)&g_psq [slot * C1 + c0] = sq;
    if ((tid & 31) == 0) g_pcnt[slot] = cnt;
}

// ---------------- kernel 4: reduce stats -> fused BN coefficients ----------
// 16 blocks x 256 threads: one warp per channel.
__global__ void k_reduce(const float* __restrict__ W1, const float* __restrict__ b1,
                         const float* __restrict__ gamma1, const float* __restrict__ beta1) {
    int c = blockIdx.x * 8 + (threadIdx.x >> 5);
    int lane = threadIdx.x & 31;
    double s0 = 0.0, s1 = 0.0, q0 = 0.0, q1 = 0.0;
    long long cnt = 0;
    for (int i = lane; i < NSLOT; i += 64) {
        s0 += (double)g_psum[i * C1 + c];
        q0 += (double)g_psq [i * C1 + c];
        s1 += (double)g_psum[(i + 32) * C1 + c];
        q1 += (double)g_psq [(i + 32) * C1 + c];
        cnt += g_pcnt[i] + g_pcnt[i + 32];
    }
    double s = s0 + s1, sq = q0 + q1;
#pragma unroll
    for (int o = 16; o > 0; o >>= 1) {
        s   += __shfl_xor_sync(0xffffffffu, s, o);
        sq  += __shfl_xor_sync(0xffffffffu, sq, o);
        cnt += __shfl_xor_sync(0xffffffffu, cnt, o);
    }
    if (lane == 0) {
        double mean = s / (double)cnt;
        double var  = sq / (double)cnt - mean * mean;
        float A = gamma1[c] / sqrtf((float)var + 1e-5f);
        g_coef[c]           = A;
        g_coef[C1 + c]      = W1[64 * C1 + c] * A;
        g_coef[2 * C1 + c]  = W1[65 * C1 + c] * A;
        g_coef[3 * C1 + c]  = beta1[c] + (b1[c] - (float)mean) * A;
    }
}

// ---------------- kernel 5: main fused (h -> tf32 mma -> max scatter) ------
// 8192 blocks x 256 threads; 4 queries (128 edge slots) per block.
// k-outermost mma loop, B re-read from smem each step -> no register spills.
__global__ void __launch_bounds__(256, 2)
k_main(const float* __restrict__ pos, const float* __restrict__ W2,
       const float* __restrict__ b2, unsigned* __restrict__ out_u) {
    extern __shared__ float sm[];
    float* hs  = sm;                        // tf32 bits, edge-major [128][HS]
    float* W2s = sm + 128 * HS;             // tf32 bits [128][WS]
    float* cfA = W2s + 128 * WS;
    float* cfX = cfA + C1;
    float* cfY = cfX + C1;
    float* cfB = cfY + C1;
    float* b2s = cfB + C1;
    float* ex2 = b2s + 64;
    float* ey2 = ex2 + 128;
    int*   es2 = (int*)(ey2 + 128);
    float* qmx = (float*)(es2 + 128);       // [4 queries][64 cols]

    int tid = threadIdx.x;
    int q0 = blockIdx.x * 4;
    const float NI = __int_as_float(0xff800000);

    for (int i = tid; i < 8192; i += 256)
        W2s[(i >> 6) * WS + (i & 63)] = __uint_as_float(f2tf32(W2[i]));
    if (tid < 128) {
        cfA[tid] = g_coef[tid];
        cfX[tid] = g_coef[C1 + tid];
        cfY[tid] = g_coef[2 * C1 + tid];
        cfB[tid] = g_coef[3 * C1 + tid];
    }
    if (tid < 64) b2s[tid] = b2[tid];
    if (tid < 128) {
        int q = q0 + (tid >> 5);
        int s = g_nbr[q * KK + (tid & 31)];
        es2[tid] = s;
        float rx = 0.f, ry = 0.f;
        if (s >= 0) {
            int d = g_pix[q];
            rx = pos[2 * s]     - pos[2 * d];
            ry = pos[2 * s + 1] - pos[2 * d + 1];
        }
        ex2[tid] = rx; ey2[tid] = ry;
    }
    __syncthreads();

    // h phase: channel = tid&127, edge half = tid>>7; edge-major tf32 store
    {
        int c = tid & 127;
        int e0h = (tid >> 7) * 64;
        float a = cfA[c], wx = cfX[c], wy = cfY[c], bb = cfB[c];
#pragma unroll 8
        for (int e = 0; e < 64; e++) {
            int ee = e0h + e;
            int s = es2[ee];
            float h = 0.f;
            if (s >= 0)
                h = fmaxf(fmaf(g_Y[s * C1 + c], a,
                          fmaf(ex2[ee], wx, fmaf(ey2[ee], wy, bb))), 0.f);
            hs[ee * HS + c] = __uint_as_float(f2tf32(h));
        }
    }
    __syncthreads();

    // mma phase: warp handles 64 edges (2 queries) x 16 cols; k outermost
    int lane = tid & 31, w = tid >> 5;
    int g = lane >> 2, t = lane & 3;
    int ng = w & 3, mg = w >> 2;
    int n0 = ng * 16;
    int e0 = mg * 64;

    float d[2][2][2][4];                 // [qq][mt][nt][4]
#pragma unroll
    for (int a1 = 0; a1 < 2; a1++)
#pragma unroll
        for (int a2 = 0; a2 < 2; a2++)
#pragma unroll
            for (int a3 = 0; a3 < 2; a3++)
#pragma unroll
                for (int a4 = 0; a4 < 4; a4++) d[a1][a2][a3][a4] = 0.f;

#pragma unroll
    for (int k = 0; k < 16; k++) {
        const float* wrow0 = W2s + (k * 8 + t) * WS + n0 + g;
        const float* wrow1 = W2s + (k * 8 + t + 4) * WS + n0 + g;
        unsigned b00 = __float_as_uint(wrow0[0]);
        unsigned b01 = __float_as_uint(wrow1[0]);
        unsigned b10 = __float_as_uint(wrow0[8]);
        unsigned b11 = __float_as_uint(wrow1[8]);
#pragma unroll
        for (int qq = 0; qq < 2; qq++)
#pragma unroll
            for (int mt = 0; mt < 2; mt++) {
                const float* hp = hs + (e0 + qq * 32 + mt * 16 + g) * HS + k * 8 + t;
                unsigned a0 = __float_as_uint(hp[0]);
                unsigned a2 = __float_as_uint(hp[4]);
                unsigned a1 = __float_as_uint(hp[8 * HS]);
                unsigned a3 = __float_as_uint(hp[8 * HS + 4]);
                asm volatile(
                    "mma.sync.aligned.m16n8k8.row.col.f32.tf32.tf32.f32 "
                    "{%0,%1,%2,%3}, {%4,%5,%6,%7}, {%8,%9}, {%0,%1,%2,%3};"
                    : "+f"(d[qq][mt][0][0]), "+f"(d[qq][mt][0][1]),
                      "+f"(d[qq][mt][0][2]), "+f"(d[qq][mt][0][3])
                    : "r"(a0), "r"(a1), "r"(a2), "r"(a3), "r"(b00), "r"(b01));
                asm volatile(
                    "mma.sync.aligned.m16n8k8.row.col.f32.tf32.tf32.f32 "
                    "{%0,%1,%2,%3}, {%4,%5,%6,%7}, {%8,%9}, {%0,%1,%2,%3};"
                    : "+f"(d[qq][mt][1][0]), "+f"(d[qq][mt][1][1]),
                      "+f"(d[qq][mt][1][2]), "+f"(d[qq][mt][1][3])
                    : "r"(a0), "r"(a1), "r"(a2), "r"(a3), "r"(b10), "r"(b11));
            }
    }

#pragma unroll
    for (int qq = 0; qq < 2; qq++) {
        float rm[2][2] = {{NI, NI}, {NI, NI}};
        int qloc = mg * 2 + qq;
#pragma unroll
        for (int mt = 0; mt < 2; mt++) {
            int eb = e0 + qq * 32 + mt * 16;
            bool vlo = es2[eb + g] >= 0;
            bool vhi = es2[eb + 8 + g] >= 0;
#pragma unroll
            for (int nt = 0; nt < 2; nt++) {
                float x0 = vlo ? d[qq][mt][nt][0] : NI;
                float x1 = vlo ? d[qq][mt][nt][1] : NI;
                float x2 = vhi ? d[qq][mt][nt][2] : NI;
                float x3 = vhi ? d[qq][mt][nt][3] : NI;
                rm[nt][0] = fmaxf(rm[nt][0], fmaxf(x0, x2));
                rm[nt][1] = fmaxf(rm[nt][1], fmaxf(x1, x3));
            }
        }
#pragma unroll
        for (int nt = 0; nt < 2; nt++)
#pragma unroll
            for (int j = 0; j < 2; j++) {
                float v = rm[nt][j];
                v = fmaxf(v, __shfl_xor_sync(0xffffffffu, v, 4));
                v = fmaxf(v, __shfl_xor_sync(0xffffffffu, v, 8));
                v = fmaxf(v, __shfl_xor_sync(0xffffffffu, v, 16));
                rm[nt][j] = v;
            }
        if (lane < 4) {
#pragma unroll
            for (int nt = 0; nt < 2; nt++) {
                qmx[qloc * 64 + n0 + nt * 8 + 2 * t]     = rm[nt][0];
                qmx[qloc * 64 + n0 + nt * 8 + 2 * t + 1] = rm[nt][1];
            }
        }
    }
    __syncthreads();

    {
        float v = qmx[tid];
        if (__float_as_uint(v) != 0xff800000u) {
            int col = tid & 63, qloc = tid >> 6;
            int q = q0 + qloc;
            int P = g_pix[q];
            atomicMax(&out_u[(P >> 10) * (FF * PP) + col * PP + (P & 1023)],
                      encf(v + b2s[col]));
        }
    }
}

// ---------------- kernel 6: self-loop messages (target = own node) ---------
__global__ void k_self(const float* __restrict__ W2, const float* __restrict__ b2,
                       unsigned* __restrict__ out_u) {
    extern __shared__ float sm[];
    float* W2s = sm;
    float* hsl = sm + 8192;
    float* cfA = hsl + 128 * HSTR2;
    float* cfB = cfA + 128;
    float* b2s = cfB + 128;

    int tid = threadIdx.x;
    int i0 = blockIdx.x * 64;

    for (int i = tid; i < 8192; i += 128) W2s[i] = W2[i];
    cfA[tid] = g_coef[tid];
    cfB[tid] = g_coef[3 * C1 + tid];
    if (tid < 64) b2s[tid] = b2[tid];
    __syncthreads();

    {
        float a = cfA[tid], bb = cfB[tid];
#pragma unroll 4
        for (int e = 0; e < 64; e++)
            hsl[tid * HSTR2 + e] = fmaxf(fmaf(g_Y[(i0 + e) * C1 + tid], a, bb), 0.f);
    }
    __syncthreads();

    int eg = tid & 15, fg = tid >> 4;
    float acc[4][8];
#pragma unroll
    for (int e = 0; e < 4; e++)
#pragma unroll
        for (int f = 0; f < 8; f++) acc[e][f] = 0.f;

    const float* hb = hsl + eg * 4;
    const float* wb = W2s + fg * 8;
    for (int c = 0; c < C1; c++) {
        float4 hv = *(const float4*)(hb + c * HSTR2);
        float4 w0 = *(const float4*)(wb + c * 64);
        float4 w1 = *(const float4*)(wb + c * 64 + 4);
        float hvv[4] = {hv.x, hv.y, hv.z, hv.w};
        float wv[8]  = {w0.x, w0.y, w0.z, w0.w, w1.x, w1.y, w1.z, w1.w};
#pragma unroll
        for (int e = 0; e < 4; e++)
#pragma unroll
            for (int f = 0; f < 8; f++)
                acc[e][f] = fmaf(hvv[e], wv[f], acc[e][f]);
    }

#pragma unroll
    for (int e = 0; e < 4; e++) {
        int node = i0 + eg * 4 + e;
        unsigned base = (unsigned)((node >> 10) * (FF * PP) + (node & 1023));
#pragma unroll
        for (int f = 0; f < 8; f++) {
            float v = acc[e][f] + b2s[fg * 8 + f];
            atomicMax(&out_u[base + (fg * 8 + f) * PP], encf(v));
        }
    }
}

// ---------------- kernel 7: decode in place ----------------
__global__ void k_decode(unsigned* __restrict__ out_u) {
    int i = blockIdx.x * 256 + threadIdx.x;
    if (i < NPTS * FF) {
        unsigned u = out_u[i];
        ((float*)out_u)[i] = decf(u);
    }
}

// ---------------- launch ----------------
extern "C" void kernel_launch(void* const* d_in, const int* in_sizes, int n_in,
                              void* d_out, int out_size) {
    const float* x      = (const float*)d_in[0];
    const float* pos    = (const float*)d_in[1];
    const int*   batch  = (const int*)  d_in[2];
    const float* W1     = (const float*)d_in[3];
    const float* b1     = (const float*)d_in[4];
    const float* gamma1 = (const float*)d_in[5];
    const float* beta1  = (const float*)d_in[6];
    const float* W2     = (const float*)d_in[7];
    const float* b2     = (const float*)d_in[8];
    unsigned* out_u = (unsigned*)d_out;

    cudaFuncSetAttribute(k_main, cudaFuncAttributeMaxDynamicSharedMemorySize, SMEM_MAIN_BYTES);
    cudaFuncSetAttribute(k_self, cudaFuncAttributeMaxDynamicSharedMemorySize, SMEM_SELF_BYTES);

    k_init  <<<(NPTS * FF + 255) / 256, 256>>>(out_u);
    k_pre   <<<NPTS / 64, 256>>>(x, pos, batch, W1);
    k_nbr   <<<NB * 4, 256>>>(pos);
    k_stats <<<STATB, 256>>>(pos, W1, b1);
    k_reduce<<<16, 256>>>(W1, b1, gamma1, beta1);
    k_main  <<<NPTS / 4, 256, SMEM_MAIN_BYTES>>>(pos, W2, b2, out_u);
    k_self  <<<NPTS / 64, 128, SMEM_SELF_BYTES>>>(W2, b2, out_u);
    k_decode<<<(NPTS * FF + 255) / 256, 256>>>(out_u);
}

// round 10
// speedup vs baseline: 2.0019x; 1.0670x over previous
#include <cuda_runtime.h>

// ---------------- problem constants ----------------
#define NPTS   32768        // B*P
#define PP     1024         // points per sample
#define NB     32           // batch
#define FF     64           // feature dim
#define KK     32           // max neighbors
#define C1     128          // hidden dim
#define NSLOT  1024         // stat partial slots (128 blocks x 8)
#define ENC_NEG_INF 0x007FFFFFu
#define CAP    128          // candidate cap in k_nbr

#define HS 136              // hs / W2t smem stride (136 mod 32 == 8 -> LDS.64 conflict-free)
// k_main smem floats: hs 128*136 | W2t 64*136 | cf 4*128 | b2s 64 | ex2 128 | ey2 128 | es2 128 | qmx 256
#define SMEM_MAIN_FLOATS (128*HS + 64*HS + 4*C1 + 64 + 128 + 128 + 128 + 256)
#define SMEM_MAIN_BYTES  (SMEM_MAIN_FLOATS * 4)

#define HSTR2 72
#define SMEM_SELF_FLOATS (8192 + 128*HSTR2 + 128 + 128 + 64)
#define SMEM_SELF_BYTES  (SMEM_SELF_FLOATS * 4)

// ---------------- device scratch (static, no allocation) ----------------
// NOTE: hidden dim stored in PERMUTED "slot" space everywhere below:
//   slot j within each 8-group: j = 2t + hi  <->  channel = t + 4*hi
// so that mma A/B fragment pairs (c, c+4) are adjacent in memory.
__device__ float    g_Y[NPTS * C1];         // x @ W1[:64], slot-space cols (16 MB)
__device__ int      g_pix[NPTS];
__device__ int      g_nbr[NPTS * KK];
__device__ float    g_psum[NSLOT * C1];
__device__ float    g_psq [NSLOT * C1];
__device__ int      g_pcnt[NSLOT];
__device__ float    g_coef[4 * C1];         // alpha | w64*a | w65*a | beta+(b1-mean)*a (slot-space)

__device__ __forceinline__ int ch_of_slot(int s) {
    int j = s & 7;
    return (s & ~7) | ((j >> 1) + ((j & 1) << 2));
}
__device__ __forceinline__ int slot_of_ch(int c) {
    int r = c & 7;
    int j = (r < 4) ? (r << 1) : ((r << 1) - 7);
    return (c & ~7) | j;
}

__device__ __forceinline__ unsigned encf(float f) {
    unsigned u = __float_as_uint(f);
    return (u & 0x80000000u) ? ~u : (u | 0x80000000u);
}
__device__ __forceinline__ float decf(unsigned u) {
    return (u & 0x80000000u) ? __uint_as_float(u & 0x7fffffffu)
                             : __uint_as_float(~u);
}
__device__ __forceinline__ unsigned f2tf32(float f) {
    unsigned u;
    asm("cvt.rna.tf32.f32 %0, %1;" : "=r"(u) : "f"(f));
    return u;
}

// depth-5 tree argmax over best[32]
__device__ __forceinline__ void tree_max32(const float* best, float& bmax, int& bpos) {
    float m16[16]; int i16[16];
#pragma unroll
    for (int k = 0; k < 16; k++) {
        bool p = best[2*k] >= best[2*k+1];
        m16[k] = p ? best[2*k] : best[2*k+1];
        i16[k] = p ? 2*k : 2*k+1;
    }
    float m8[8]; int i8[8];
#pragma unroll
    for (int k = 0; k < 8; k++) {
        bool p = m16[2*k] >= m16[2*k+1];
        m8[k] = p ? m16[2*k] : m16[2*k+1];
        i8[k] = p ? i16[2*k] : i16[2*k+1];
    }
    float m4[4]; int i4[4];
#pragma unroll
    for (int k = 0; k < 4; k++) {
        bool p = m8[2*k] >= m8[2*k+1];
        m4[k] = p ? m8[2*k] : m8[2*k+1];
        i4[k] = p ? i8[2*k] : i8[2*k+1];
    }
    float m2[2]; int i2[2];
#pragma unroll
    for (int k = 0; k < 2; k++) {
        bool p = m4[2*k] >= m4[2*k+1];
        m2[k] = p ? m4[2*k] : m4[2*k+1];
        i2[k] = p ? i4[2*k] : i4[2*k+1];
    }
    bool p = m2[0] >= m2[1];
    bmax = p ? m2[0] : m2[1];
    bpos = p ? i2[0] : i2[1];
}

// ---------------- kernel 1: out init + pixel index + Y = x @ W1[:64] -------
// 512 blocks x 256 threads, 64 points per block. g_Y written in slot space.
__global__ void k_pre(const float* __restrict__ x, const float* __restrict__ pos,
                      const int* __restrict__ batch, const float* __restrict__ W1,
                      unsigned* __restrict__ out_u) {
    __shared__ float w1s[64 * C1];
    __shared__ float xs[64 * FF];
    int tid = threadIdx.x;
    int p0 = blockIdx.x * 64;

    // init output accumulator (2M uints over 512 blocks)
    {
        uint4 v = make_uint4(ENC_NEG_INF, ENC_NEG_INF, ENC_NEG_INF, ENC_NEG_INF);
        uint4* o4 = (uint4*)out_u;
        int b4 = blockIdx.x * 1024 + tid;
        o4[b4] = v; o4[b4 + 256] = v; o4[b4 + 512] = v; o4[b4 + 768] = v;
    }

    // stage W1[:64] with column permutation -> slot space
    for (int i = tid; i < 64 * C1; i += 256) {
        int r = i >> 7, sl = i & 127;
        w1s[i] = W1[r * C1 + ch_of_slot(sl)];
    }
    for (int i = tid; i < 64 * FF; i += 256) xs[i] = x[p0 * FF + i];
    if (tid < 64) {
        int i = p0 + tid;
        float px = pos[2 * i], py = pos[2 * i + 1];
        int col = (int)(px * 32.0f); col = min(max(col, 0), 31);
        int row = (int)(py * 32.0f); row = min(max(row, 0), 31);
        g_pix[i] = batch[i] * (NB * NB) + row * 32 + col;
    }
    __syncthreads();

    int pg = tid >> 5;
    int c0 = (tid & 31) * 4;
    float acc[8][4];
#pragma unroll
    for (int p = 0; p < 8; p++)
#pragma unroll
        for (int c = 0; c < 4; c++) acc[p][c] = 0.f;

    for (int r = 0; r < 64; r++) {
        float4 w = *(const float4*)&w1s[r * C1 + c0];
#pragma unroll
        for (int p = 0; p < 8; p++) {
            float xv = xs[(pg * 8 + p) * FF + r];
            acc[p][0] = fmaf(xv, w.x, acc[p][0]);
            acc[p][1] = fmaf(xv, w.y, acc[p][1]);
            acc[p][2] = fmaf(xv, w.z, acc[p][2]);
            acc[p][3] = fmaf(xv, w.w, acc[p][3]);
        }
    }
#pragma unroll
    for (int p = 0; p < 8; p++) {
        int pt = p0 + pg * 8 + p;
        *(float4*)&g_Y[pt * C1 + c0] =
            make_float4(acc[p][0], acc[p][1], acc[p][2], acc[p][3]);
    }
}

// ---------------- kernel 2: ball-query K-NN + BN partial stats (fused) -----
// 128 blocks x 256 threads; block owns 256 queries of one batch sample.
__global__ void k_nbrstats(const float* __restrict__ pos, const float* __restrict__ W1,
                           const float* __restrict__ b1) {
    __shared__ float2 ps[PP];        // 8 KB
    __shared__ int    nbr_sm[256 * KK];  // 32 KB
    __shared__ int    pixl[256];     // 1 KB
    int tid = threadIdx.x;
    int b = blockIdx.x >> 2;
    int q0g = b * PP + ((blockIdx.x & 3) << 8);
    const float2* pb = (const float2*)pos + b * PP;
    for (int i = tid; i < PP; i += 256) ps[i] = pb[i];
    pixl[tid] = g_pix[q0g + tid];
    __syncthreads();

    // ---- phase A: radius K-NN for query tid ----
    {
        int ql = (q0g & 1023) + tid;
        float qx = ps[ql].x, qy = ps[ql].y;
        const float R2 = 0.01f;
        const float INF = __int_as_float(0x7f800000);
        int pixq = pixl[tid];

        float cd2[CAP];
        int   cj [CAP];
        int c = 0;
        for (int j = 0; j < PP; j++) {
            float dx = __fsub_rn(qx, ps[j].x);
            float dy = __fsub_rn(qy, ps[j].y);
            float d2 = __fadd_rn(__fmul_rn(dx, dx), __fmul_rn(dy, dy));
            if (d2 <= R2) {
                if (c < CAP) { cd2[c] = d2; cj[c] = j; }
                c++;
            }
        }

        int kout = 0;
        if (c <= CAP) {
            float t = INF;
            int quota = 0;
            bool need_sel = (c > KK);
            if (need_sel) {
                float best[32];
#pragma unroll
                for (int k = 0; k < 32; k++) best[k] = cd2[k];
                float bmax; int bpos;
                tree_max32(best, bmax, bpos);
                for (int i = 32; i < c; i++) {
                    float d = cd2[i];
                    if (d < bmax) {
#pragma unroll
                        for (int k = 0; k < 32; k++) best[k] = (k == bpos) ? d : best[k];
                        tree_max32(best, bmax, bpos);
                    }
                }
                t = bmax;
                int c1 = 0;
                for (int i = 0; i < c; i++) c1 += (cd2[i] < t) ? 1 : 0;
                quota = KK - c1;
            }
            for (int i = 0; i < c; i++) {
                bool take;
                if (!need_sel) take = true;
                else {
                    float d = cd2[i];
                    if (d < t) take = true;
                    else if (d == t && quota > 0) { take = true; quota--; }
                    else take = false;
                }
                if (take) {
                    int s = b * PP + cj[i];
                    if (s != pixq) nbr_sm[tid * KK + (kout++)] = s;
                }
            }
        } else {
            // overflow fallback: full streaming selection (never expected)
            float best[32];
#pragma unroll
            for (int k = 0; k < 32; k++) best[k] = INF;
            float bmax = INF; int bpos = 0;
            for (int j = 0; j < PP; j++) {
                float dx = __fsub_rn(qx, ps[j].x);
                float dy = __fsub_rn(qy, ps[j].y);
                float d2 = __fadd_rn(__fmul_rn(dx, dx), __fmul_rn(dy, dy));
                if (d2 <= R2 && d2 < bmax) {
#pragma unroll
                    for (int k = 0; k < 32; k++) best[k] = (k == bpos) ? d2 : best[k];
                    tree_max32(best, bmax, bpos);
                }
            }
            float t = bmax;
            int c1 = 0;
            for (int j = 0; j < PP; j++) {
                float dx = __fsub_rn(qx, ps[j].x);
                float dy = __fsub_rn(qy, ps[j].y);
                float d2 = __fadd_rn(__fmul_rn(dx, dx), __fmul_rn(dy, dy));
                c1 += (d2 <= R2 && d2 < t) ? 1 : 0;
            }
            int quota = KK - c1;
            for (int j = 0; j < PP; j++) {
                float dx = __fsub_rn(qx, ps[j].x);
                float dy = __fsub_rn(qy, ps[j].y);
                float d2 = __fadd_rn(__fmul_rn(dx, dx), __fmul_rn(dy, dy));
                if (d2 > R2) continue;
                bool take = false;
                if (d2 < t) take = true;
                else if (d2 == t && quota > 0) { take = true; quota--; }
                if (take) {
                    int s = b * PP + j;
                    if (s != pixq) nbr_sm[tid * KK + (kout++)] = s;
                }
            }
        }
        for (; kout < KK; kout++) nbr_sm[tid * KK + kout] = -1;
    }
    __syncthreads();

    // copy neighbor lists to global (vectorized, coalesced)
    {
        const int4* src = (const int4*)nbr_sm;
        int4* dst = (int4*)&g_nbr[q0g * KK];
#pragma unroll
        for (int i = 0; i < 8; i++) dst[i * 256 + tid] = src[i * 256 + tid];
    }

    // ---- phase B: BN partial stats over this block's 8448 messages ----
    {
        int c4 = (tid & 31) * 4;        // 4 slots per thread
        int part = tid >> 5;            // 8 partials, 1056 messages each
        float w64v[4], w65v[4], b1v[4];
#pragma unroll
        for (int u = 0; u < 4; u++) {
            int ch = ch_of_slot(c4 + u);
            w64v[u] = W1[64 * C1 + ch];
            w65v[u] = W1[65 * C1 + ch];
            b1v[u]  = b1[ch];
        }
        float sum[4] = {0.f, 0.f, 0.f, 0.f};
        float sq [4] = {0.f, 0.f, 0.f, 0.f};
        int cnt = 0;
        int m0 = part * 1056;
#pragma unroll 4
        for (int m = m0; m < m0 + 1056; m++) {
            int s; float rx, ry;
            if (m < 8192) {
                s = nbr_sm[m];
                if (s < 0) continue;
                int j = s & 1023;
                int dl = pixl[m >> 5] & 1023;
                rx = ps[j].x - ps[dl].x;
                ry = ps[j].y - ps[dl].y;
            } else {
                s = q0g + (m - 8192);
                rx = 0.f; ry = 0.f;
            }
            cnt++;
            float4 y = *(const float4*)&g_Y[s * C1 + c4];
            float z0 = fmaf(rx, w64v[0], fmaf(ry, w65v[0], y.x + b1v[0]));
            float z1 = fmaf(rx, w64v[1], fmaf(ry, w65v[1], y.y + b1v[1]));
            float z2 = fmaf(rx, w64v[2], fmaf(ry, w65v[2], y.z + b1v[2]));
            float z3 = fmaf(rx, w64v[3], fmaf(ry, w65v[3], y.w + b1v[3]));
            sum[0] += z0; sum[1] += z1; sum[2] += z2; sum[3] += z3;
            sq[0] = fmaf(z0, z0, sq[0]); sq[1] = fmaf(z1, z1, sq[1]);
            sq[2] = fmaf(z2, z2, sq[2]); sq[3] = fmaf(z3, z3, sq[3]);
        }
        int slot = blockIdx.x * 8 + part;
        *(float4*)&g_psum[slot * C1 + c4] = make_float4(sum[0], sum[1], sum[2], sum[3]);
        *(float4*)&g_psq [slot * C1 + c4] = make_float4(sq[0], sq[1], sq[2], sq[3]);
        if ((tid & 31) == 0) g_pcnt[slot] = cnt;
    }
}

// ---------------- kernel 3: reduce stats -> fused BN coefficients ----------
// 16 blocks x 256 threads: one warp per slot(channel).
__global__ void k_reduce(const float* __restrict__ W1, const float* __restrict__ b1,
                         const float* __restrict__ gamma1, const float* __restrict__ beta1) {
    int c = blockIdx.x * 8 + (threadIdx.x >> 5);   // slot
    int lane = threadIdx.x & 31;
    double s = 0.0, sq = 0.0;
    long long cnt = 0;
    for (int i = lane; i < NSLOT; i += 32) {
        s  += (double)g_psum[i * C1 + c];
        sq += (double)g_psq [i * C1 + c];
        cnt += g_pcnt[i];
    }
#pragma unroll
    for (int o = 16; o > 0; o >>= 1) {
        s   += __shfl_xor_sync(0xffffffffu, s, o);
        sq  += __shfl_xor_sync(0xffffffffu, sq, o);
        cnt += __shfl_xor_sync(0xffffffffu, cnt, o);
    }
    if (lane == 0) {
        int ch = ch_of_slot(c);
        double mean = s / (double)cnt;
        double var  = sq / (double)cnt - mean * mean;
        float A = gamma1[ch] / sqrtf((float)var + 1e-5f);
        g_coef[c]           = A;
        g_coef[C1 + c]      = W1[64 * C1 + ch] * A;
        g_coef[2 * C1 + c]  = W1[65 * C1 + ch] * A;
        g_coef[3 * C1 + c]  = beta1[ch] + (b1[ch] - (float)mean) * A;
    }
}

// ---------------- kernel 4: main fused (h -> tf32 mma -> max scatter) ------
// 8192 blocks x 256 threads; 4 queries (128 edge slots) per block.
__global__ void __launch_bounds__(256, 2)
k_main(const float* __restrict__ pos, const float* __restrict__ W2,
       const float* __restrict__ b2, unsigned* __restrict__ out_u) {
    extern __shared__ float sm[];
    float* hs  = sm;                        // tf32 bits, edge-major [128][HS], slot cols
    float* W2t = sm + 128 * HS;             // tf32 bits, col-major [64][HS], slot rows
    float* cfA = W2t + 64 * HS;
    float* cfX = cfA + C1;
    float* cfY = cfX + C1;
    float* cfB = cfY + C1;
    float* b2s = cfB + C1;
    float* ex2 = b2s + 64;
    float* ey2 = ex2 + 128;
    int*   es2 = (int*)(ey2 + 128);
    float* qmx = (float*)(es2 + 128);       // [4 queries][64 cols]

    int tid = threadIdx.x;
    int q0 = blockIdx.x * 4;
    const float NI = __int_as_float(0xff800000);

    // stage W2 transposed + row-permuted, pre-converted to tf32
    for (int i = tid; i < 8192; i += 256) {
        int c = i >> 6, n = i & 63;
        W2t[n * HS + slot_of_ch(c)] = __uint_as_float(f2tf32(W2[i]));
    }
    if (tid < 128) {
        cfA[tid] = g_coef[tid];
        cfX[tid] = g_coef[C1 + tid];
        cfY[tid] = g_coef[2 * C1 + tid];
        cfB[tid] = g_coef[3 * C1 + tid];
    }
    if (tid < 64) b2s[tid] = b2[tid];
    if (tid < 128) {
        int q = q0 + (tid >> 5);
        int s = g_nbr[q * KK + (tid & 31)];
        es2[tid] = s;
        float rx = 0.f, ry = 0.f;
        if (s >= 0) {
            int d = g_pix[q];
            rx = pos[2 * s]     - pos[2 * d];
            ry = pos[2 * s + 1] - pos[2 * d + 1];
        }
        ex2[tid] = rx; ey2[tid] = ry;
    }
    __syncthreads();

    // h phase: float4 over 4 slots x 16 edges per thread
    {
        int c4 = (tid & 31) * 4;
        int grp = tid >> 5;
        float4 av = *(const float4*)&cfA[c4];
        float4 xv = *(const float4*)&cfX[c4];
        float4 yv = *(const float4*)&cfY[c4];
        float4 bv = *(const float4*)&cfB[c4];
#pragma unroll 4
        for (int e = 0; e < 16; e++) {
            int ee = grp * 16 + e;
            int s = es2[ee];
            float4 h = make_float4(0.f, 0.f, 0.f, 0.f);
            if (s >= 0) {
                float4 y = *(const float4*)&g_Y[s * C1 + c4];
                float rx = ex2[ee], ry = ey2[ee];
                h.x = fmaxf(fmaf(y.x, av.x, fmaf(rx, xv.x, fmaf(ry, yv.x, bv.x))), 0.f);
                h.y = fmaxf(fmaf(y.y, av.y, fmaf(rx, xv.y, fmaf(ry, yv.y, bv.y))), 0.f);
                h.z = fmaxf(fmaf(y.z, av.z, fmaf(rx, xv.z, fmaf(ry, yv.z, bv.z))), 0.f);
                h.w = fmaxf(fmaf(y.w, av.w, fmaf(rx, xv.w, fmaf(ry, yv.w, bv.w))), 0.f);
            }
            float4 ht;
            ht.x = __uint_as_float(f2tf32(h.x));
            ht.y = __uint_as_float(f2tf32(h.y));
            ht.z = __uint_as_float(f2tf32(h.z));
            ht.w = __uint_as_float(f2tf32(h.w));
            *(float4*)&hs[ee * HS + c4] = ht;
        }
    }
    __syncthreads();

    // mma phase: warp = 64 edges (2 queries) x 16 cols; k outermost
    int lane = tid & 31, w = tid >> 5;
    int g = lane >> 2, t = lane & 3;
    int ng = w & 3, mg = w >> 2;
    int n0 = ng * 16;
    int e0 = mg * 64;

    float d[2][2][2][4];
#pragma unroll
    for (int a1 = 0; a1 < 2; a1++)
#pragma unroll
        for (int a2 = 0; a2 < 2; a2++)
#pragma unroll
            for (int a3 = 0; a3 < 2; a3++)
#pragma unroll
                for (int a4 = 0; a4 < 4; a4++) d[a1][a2][a3][a4] = 0.f;

#pragma unroll
    for (int k = 0; k < 16; k++) {
        // B fragments: k-rows (t, t+4) are adjacent slots (2t, 2t+1)
        float2 bv0 = *(const float2*)&W2t[(n0 + g)     * HS + k * 8 + 2 * t];
        float2 bv1 = *(const float2*)&W2t[(n0 + g + 8) * HS + k * 8 + 2 * t];
        unsigned b00 = __float_as_uint(bv0.x), b01 = __float_as_uint(bv0.y);
        unsigned b10 = __float_as_uint(bv1.x), b11 = __float_as_uint(bv1.y);
#pragma unroll
        for (int qq = 0; qq < 2; qq++)
#pragma unroll
            for (int mt = 0; mt < 2; mt++) {
                const float* hp = hs + (e0 + qq * 32 + mt * 16 + g) * HS + k * 8 + 2 * t;
                float2 alo = *(const float2*)hp;             // A[g][t], A[g][t+4]
                float2 ahi = *(const float2*)(hp + 8 * HS);  // A[g+8][t], A[g+8][t+4]
                unsigned a0 = __float_as_uint(alo.x);
                unsigned a2 = __float_as_uint(alo.y);
                unsigned a1 = __float_as_uint(ahi.x);
                unsigned a3 = __float_as_uint(ahi.y);
                asm volatile(
                    "mma.sync.aligned.m16n8k8.row.col.f32.tf32.tf32.f32 "
                    "{%0,%1,%2,%3}, {%4,%5,%6,%7}, {%8,%9}, {%0,%1,%2,%3};"
                    : "+f"(d[qq][mt][0][0]), "+f"(d[qq][mt][0][1]),
                      "+f"(d[qq][mt][0][2]), "+f"(d[qq][mt][0][3])
                    : "r"(a0), "r"(a1), "r"(a2), "r"(a3), "r"(b00), "r"(b01));
                asm volatile(
                    "mma.sync.aligned.m16n8k8.row.col.f32.tf32.tf32.f32 "
                    "{%0,%1,%2,%3}, {%4,%5,%6,%7}, {%8,%9}, {%0,%1,%2,%3};"
                    : "+f"(d[qq][mt][1][0]), "+f"(d[qq][mt][1][1]),
                      "+f"(d[qq][mt][1][2]), "+f"(d[qq][mt][1][3])
                    : "r"(a0), "r"(a1), "r"(a2), "r"(a3), "r"(b10), "r"(b11));
            }
    }

#pragma unroll
    for (int qq = 0; qq < 2; qq++) {
        float rm[2][2] = {{NI, NI}, {NI, NI}};
        int qloc = mg * 2 + qq;
#pragma unroll
        for (int mt = 0; mt < 2; mt++) {
            int eb = e0 + qq * 32 + mt * 16;
            bool vlo = es2[eb + g] >= 0;
            bool vhi = es2[eb + 8 + g] >= 0;
#pragma unroll
            for (int nt = 0; nt < 2; nt++) {
                float x0 = vlo ? d[qq][mt][nt][0] : NI;
                float x1 = vlo ? d[qq][mt][nt][1] : NI;
                float x2 = vhi ? d[qq][mt][nt][2] : NI;
                float x3 = vhi ? d[qq][mt][nt][3] : NI;
                rm[nt][0] = fmaxf(rm[nt][0], fmaxf(x0, x2));
                rm[nt][1] = fmaxf(rm[nt][1], fmaxf(x1, x3));
            }
        }
#pragma unroll
        for (int nt = 0; nt < 2; nt++)
#pragma unroll
            for (int j = 0; j < 2; j++) {
                float v = rm[nt][j];
                v = fmaxf(v, __shfl_xor_sync(0xffffffffu, v, 4));
                v = fmaxf(v, __shfl_xor_sync(0xffffffffu, v, 8));
                v = fmaxf(v, __shfl_xor_sync(0xffffffffu, v, 16));
                rm[nt][j] = v;
            }
        if (lane < 4) {
#pragma unroll
            for (int nt = 0; nt < 2; nt++) {
                qmx[qloc * 64 + n0 + nt * 8 + 2 * t]     = rm[nt][0];
                qmx[qloc * 64 + n0 + nt * 8 + 2 * t + 1] = rm[nt][1];
            }
        }
    }
    __syncthreads();

    {
        float v = qmx[tid];
        if (__float_as_uint(v) != 0xff800000u) {
            int col = tid & 63, qloc = tid >> 6;
            int q = q0 + qloc;
            int P = g_pix[q];
            atomicMax(&out_u[(P >> 10) * (FF * PP) + col * PP + (P & 1023)],
                      encf(v + b2s[col]));
        }
    }
}

// ---------------- kernel 5: self-loop messages (target = own node) ---------
__global__ void k_self(const float* __restrict__ W2, const float* __restrict__ b2,
                       unsigned* __restrict__ out_u) {
    extern __shared__ float sm[];
    float* W2s = sm;                 // [128 slot-rows][64]
    float* hsl = sm + 8192;
    float* cfA = hsl + 128 * HSTR2;
    float* cfB = cfA + 128;
    float* b2s = cfB + 128;

    int tid = threadIdx.x;
    int i0 = blockIdx.x * 64;

    for (int i = tid; i < 8192; i += 128) {
        int c = i >> 6, n = i & 63;
        W2s[slot_of_ch(c) * 64 + n] = W2[i];
    }
    cfA[tid] = g_coef[tid];
    cfB[tid] = g_coef[3 * C1 + tid];
    if (tid < 64) b2s[tid] = b2[tid];
    __syncthreads();

    {
        float a = cfA[tid], bb = cfB[tid];
#pragma unroll 4
        for (int e = 0; e < 64; e++)
            hsl[tid * HSTR2 + e] = fmaxf(fmaf(g_Y[(i0 + e) * C1 + tid], a, bb), 0.f);
    }
    __syncthreads();

    int eg = tid & 15, fg = tid >> 4;
    float acc[4][8];
#pragma unroll
    for (int e = 0; e < 4; e++)
#pragma unroll
        for (int f = 0; f < 8; f++) acc[e][f] = 0.f;

    const float* hb = hsl + eg * 4;
    const float* wb = W2s + fg * 8;
    for (int c = 0; c < C1; c++) {
        float4 hv = *(const float4*)(hb + c * HSTR2);
        float4 w0 = *(const float4*)(wb + c * 64);
        float4 w1 = *(const float4*)(wb + c * 64 + 4);
        float hvv[4] = {hv.x, hv.y, hv.z, hv.w};
        float wv[8]  = {w0.x, w0.y, w0.z, w0.w, w1.x, w1.y, w1.z, w1.w};
#pragma unroll
        for (int e = 0; e < 4; e++)
#pragma unroll
            for (int f = 0; f < 8; f++)
                acc[e][f] = fmaf(hvv[e], wv[f], acc[e][f]);
    }

#pragma unroll
    for (int e = 0; e < 4; e++) {
        int node = i0 + eg * 4 + e;
        unsigned base = (unsigned)((node >> 10) * (FF * PP) + (node & 1023));
#pragma unroll
        for (int f = 0; f < 8; f++) {
            float v = acc[e][f] + b2s[fg * 8 + f];
            atomicMax(&out_u[base + (fg * 8 + f) * PP], encf(v));
        }
    }
}

// ---------------- kernel 6: decode in place ----------------
__global__ void k_decode(unsigned* __restrict__ out_u) {
    int i = blockIdx.x * 256 + threadIdx.x;
    if (i < NPTS * FF) {
        unsigned u = out_u[i];
        ((float*)out_u)[i] = decf(u);
    }
}

// ---------------- launch ----------------
extern "C" void kernel_launch(void* const* d_in, const int* in_sizes, int n_in,
                              void* d_out, int out_size) {
    const float* x      = (const float*)d_in[0];
    const float* pos    = (const float*)d_in[1];
    const int*   batch  = (const int*)  d_in[2];
    const float* W1     = (const float*)d_in[3];
    const float* b1     = (const float*)d_in[4];
    const float* gamma1 = (const float*)d_in[5];
    const float* beta1  = (const float*)d_in[6];
    const float* W2     = (const float*)d_in[7];
    const float* b2     = (const float*)d_in[8];
    unsigned* out_u = (unsigned*)d_out;

    cudaFuncSetAttribute(k_main, cudaFuncAttributeMaxDynamicSharedMemorySize, SMEM_MAIN_BYTES);
    cudaFuncSetAttribute(k_self, cudaFuncAttributeMaxDynamicSharedMemorySize, SMEM_SELF_BYTES);

    k_pre     <<<NPTS / 64, 256>>>(x, pos, batch, W1, out_u);
    k_nbrstats<<<NB * 4, 256>>>(pos, W1, b1);
    k_reduce  <<<16, 256>>>(W1, b1, gamma1, beta1);
    k_main    <<<NPTS / 4, 256, SMEM_MAIN_BYTES>>>(pos, W2, b2, out_u);
    k_self    <<<NPTS / 64, 128, SMEM_SELF_BYTES>>>(W2, b2, out_u);
    k_decode  <<<(NPTS * FF + 255) / 256, 256>>>(out_u);
}

// round 11
// speedup vs baseline: 2.3182x; 1.1580x over previous
#include <cuda_runtime.h>

// ---------------- problem constants ----------------
#define NPTS   32768        // B*P
#define PP     1024         // points per sample
#define NB     32           // batch
#define FF     64           // feature dim
#define KK     32           // max neighbors
#define C1     128          // hidden dim
#define NSLOT  1024         // stat partial slots (128 blocks x 8)
#define ENC_NEG_INF 0x007FFFFFu
#define CAP    128          // candidate cap in k_nbr

#define HSH 72              // hs stride: 64 slots + 8 pad (72 mod 32 == 8)
#define WS  136             // W2t smem stride: 128 slots + 8 pad
// k_main smem floats: hs 128*72 | W2t 64*136 | ex2 128 | ey2 128 | es2 128 | qmx 256
#define SMEM_MAIN_FLOATS (128*HSH + 64*WS + 128 + 128 + 128 + 256)
#define SMEM_MAIN_BYTES  (SMEM_MAIN_FLOATS * 4)

#define HSTR2 72
#define SMEM_SELF_FLOATS (8192 + 128*HSTR2 + 128 + 128 + 64)
#define SMEM_SELF_BYTES  (SMEM_SELF_FLOATS * 4)

// ---------------- device scratch (static, no allocation) ----------------
// hidden dim stored in PERMUTED "slot" space: slot j = 2t + hi <-> channel t + 4*hi
__device__ float    g_Y[NPTS * C1];         // x @ W1[:64], slot cols (16 MB)
__device__ int      g_pix[NPTS];
__device__ int      g_nbr[NPTS * KK];
__device__ float    g_psum[NSLOT * C1];
__device__ float    g_psq [NSLOT * C1];
__device__ int      g_pcnt[NSLOT];
__device__ float    g_coef[4 * C1];         // alpha | w64*a | w65*a | beta+(b1-mean)*a (slot space)
__device__ float    g_W2t[64 * C1];         // W2 transposed [n][slot], tf32 bits

__device__ __forceinline__ int ch_of_slot(int s) {
    int j = s & 7;
    return (s & ~7) | ((j >> 1) + ((j & 1) << 2));
}
__device__ __forceinline__ int slot_of_ch(int c) {
    int r = c & 7;
    int j = (r < 4) ? (r << 1) : ((r << 1) - 7);
    return (c & ~7) | j;
}

__device__ __forceinline__ unsigned encf(float f) {
    unsigned u = __float_as_uint(f);
    return (u & 0x80000000u) ? ~u : (u | 0x80000000u);
}
__device__ __forceinline__ float decf(unsigned u) {
    return (u & 0x80000000u) ? __uint_as_float(u & 0x7fffffffu)
                             : __uint_as_float(~u);
}
__device__ __forceinline__ unsigned f2tf32(float f) {
    unsigned u;
    asm("cvt.rna.tf32.f32 %0, %1;" : "=r"(u) : "f"(f));
    return u;
}

// depth-5 tree argmax over best[32]
__device__ __forceinline__ void tree_max32(const float* best, float& bmax, int& bpos) {
    float m16[16]; int i16[16];
#pragma unroll
    for (int k = 0; k < 16; k++) {
        bool p = best[2*k] >= best[2*k+1];
        m16[k] = p ? best[2*k] : best[2*k+1];
        i16[k] = p ? 2*k : 2*k+1;
    }
    float m8[8]; int i8[8];
#pragma unroll
    for (int k = 0; k < 8; k++) {
        bool p = m16[2*k] >= m16[2*k+1];
        m8[k] = p ? m16[2*k] : m16[2*k+1];
        i8[k] = p ? i16[2*k] : i16[2*k+1];
    }
    float m4[4]; int i4[4];
#pragma unroll
    for (int k = 0; k < 4; k++) {
        bool p = m8[2*k] >= m8[2*k+1];
        m4[k] = p ? m8[2*k] : m8[2*k+1];
        i4[k] = p ? i8[2*k] : i8[2*k+1];
    }
    float m2[2]; int i2[2];
#pragma unroll
    for (int k = 0; k < 2; k++) {
        bool p = m4[2*k] >= m4[2*k+1];
        m2[k] = p ? m4[2*k] : m4[2*k+1];
        i2[k] = p ? i4[2*k] : i4[2*k+1];
    }
    bool p = m2[0] >= m2[1];
    bmax = p ? m2[0] : m2[1];
    bpos = p ? i2[0] : i2[1];
}

// ---------------- kernel 1: init output accumulator ----------------
__global__ void k_init(unsigned* __restrict__ out_u) {
    int i = blockIdx.x * 256 + threadIdx.x;
    if (i < NPTS * FF) out_u[i] = ENC_NEG_INF;
}

// ---------------- kernel 2: pixel index + Y = x @ W1[:64] ----------------
__global__ void k_pre(const float* __restrict__ x, const float* __restrict__ pos,
                      const int* __restrict__ batch, const float* __restrict__ W1) {
    __shared__ float w1s[64 * C1];
    __shared__ float xs[64 * FF];
    int tid = threadIdx.x;
    int p0 = blockIdx.x * 64;

    for (int i = tid; i < 64 * C1; i += 256) {
        int r = i >> 7, sl = i & 127;
        w1s[i] = W1[r * C1 + ch_of_slot(sl)];
    }
    for (int i = tid; i < 64 * FF; i += 256) xs[i] = x[p0 * FF + i];
    if (tid < 64) {
        int i = p0 + tid;
        float px = pos[2 * i], py = pos[2 * i + 1];
        int col = (int)(px * 32.0f); col = min(max(col, 0), 31);
        int row = (int)(py * 32.0f); row = min(max(row, 0), 31);
        g_pix[i] = batch[i] * (NB * NB) + row * 32 + col;
    }
    __syncthreads();

    int pg = tid >> 5;
    int c0 = (tid & 31) * 4;
    float acc[8][4];
#pragma unroll
    for (int p = 0; p < 8; p++)
#pragma unroll
        for (int c = 0; c < 4; c++) acc[p][c] = 0.f;

    for (int r = 0; r < 64; r++) {
        float4 w = *(const float4*)&w1s[r * C1 + c0];
#pragma unroll
        for (int p = 0; p < 8; p++) {
            float xv = xs[(pg * 8 + p) * FF + r];
            acc[p][0] = fmaf(xv, w.x, acc[p][0]);
            acc[p][1] = fmaf(xv, w.y, acc[p][1]);
            acc[p][2] = fmaf(xv, w.z, acc[p][2]);
            acc[p][3] = fmaf(xv, w.w, acc[p][3]);
        }
    }
#pragma unroll
    for (int p = 0; p < 8; p++) {
        int pt = p0 + pg * 8 + p;
        *(float4*)&g_Y[pt * C1 + c0] =
            make_float4(acc[p][0], acc[p][1], acc[p][2], acc[p][3]);
    }
}

// ---------------- kernel 3: W2 -> global transposed slot-space tf32 --------
__global__ void k_w2(const float* __restrict__ W2) {
    int i = blockIdx.x * 256 + threadIdx.x;   // 32 blocks x 256
    if (i < 64 * C1) {
        int n = i >> 7, sl = i & 127;
        g_W2t[n * C1 + sl] = __uint_as_float(f2tf32(W2[ch_of_slot(sl) * 64 + n]));
    }
}

// ---------------- kernel 4: ball-query K-NN + BN partial stats (fused) -----
// 128 blocks x 256 threads. Launch slot #4 -> ncu-profiled this round.
__global__ void k_nbrstats(const float* __restrict__ pos, const float* __restrict__ W1,
                           const float* __restrict__ b1) {
    __shared__ float2 ps[PP];
    __shared__ int    nbr_sm[256 * KK];
    __shared__ int    pixl[256];
    int tid = threadIdx.x;
    int b = blockIdx.x >> 2;
    int q0g = b * PP + ((blockIdx.x & 3) << 8);
    const float2* pb = (const float2*)pos + b * PP;
    for (int i = tid; i < PP; i += 256) ps[i] = pb[i];
    pixl[tid] = g_pix[q0g + tid];
    __syncthreads();

    // ---- phase A: radius K-NN for query tid ----
    {
        int ql = (q0g & 1023) + tid;
        float qx = ps[ql].x, qy = ps[ql].y;
        const float R2 = 0.01f;
        const float INF = __int_as_float(0x7f800000);
        int pixq = pixl[tid];

        float cd2[CAP];
        int   cj [CAP];
        int c = 0;
        for (int j = 0; j < PP; j++) {
            float dx = __fsub_rn(qx, ps[j].x);
            float dy = __fsub_rn(qy, ps[j].y);
            float d2 = __fadd_rn(__fmul_rn(dx, dx), __fmul_rn(dy, dy));
            if (d2 <= R2) {
                if (c < CAP) { cd2[c] = d2; cj[c] = j; }
                c++;
            }
        }

        int kout = 0;
        if (c <= CAP) {
            float t = INF;
            int quota = 0;
            bool need_sel = (c > KK);
            if (need_sel) {
                float best[32];
#pragma unroll
                for (int k = 0; k < 32; k++) best[k] = cd2[k];
                float bmax; int bpos;
                tree_max32(best, bmax, bpos);
                for (int i = 32; i < c; i++) {
                    float d = cd2[i];
                    if (d < bmax) {
#pragma unroll
                        for (int k = 0; k < 32; k++) best[k] = (k == bpos) ? d : best[k];
                        tree_max32(best, bmax, bpos);
                    }
                }
                t = bmax;
                int c1 = 0;
                for (int i = 0; i < c; i++) c1 += (cd2[i] < t) ? 1 : 0;
                quota = KK - c1;
            }
            for (int i = 0; i < c; i++) {
                bool take;
                if (!need_sel) take = true;
                else {
                    float d = cd2[i];
                    if (d < t) take = true;
                    else if (d == t && quota > 0) { take = true; quota--; }
                    else take = false;
                }
                if (take) {
                    int s = b * PP + cj[i];
                    if (s != pixq) nbr_sm[tid * KK + (kout++)] = s;
                }
            }
        } else {
            // overflow fallback (never expected): full streaming selection
            float best[32];
#pragma unroll
            for (int k = 0; k < 32; k++) best[k] = INF;
            float bmax = INF; int bpos = 0;
            for (int j = 0; j < PP; j++) {
                float dx = __fsub_rn(qx, ps[j].x);
                float dy = __fsub_rn(qy, ps[j].y);
                float d2 = __fadd_rn(__fmul_rn(dx, dx), __fmul_rn(dy, dy));
                if (d2 <= R2 && d2 < bmax) {
#pragma unroll
                    for (int k = 0; k < 32; k++) best[k] = (k == bpos) ? d2 : best[k];
                    tree_max32(best, bmax, bpos);
                }
            }
            float t = bmax;
            int c1 = 0;
            for (int j = 0; j < PP; j++) {
                float dx = __fsub_rn(qx, ps[j].x);
                float dy = __fsub_rn(qy, ps[j].y);
                float d2 = __fadd_rn(__fmul_rn(dx, dx), __fmul_rn(dy, dy));
                c1 += (d2 <= R2 && d2 < t) ? 1 : 0;
            }
            int quota = KK - c1;
            for (int j = 0; j < PP; j++) {
                float dx = __fsub_rn(qx, ps[j].x);
                float dy = __fsub_rn(qy, ps[j].y);
                float d2 = __fadd_rn(__fmul_rn(dx, dx), __fmul_rn(dy, dy));
                if (d2 > R2) continue;
                bool take = false;
                if (d2 < t) take = true;
                else if (d2 == t && quota > 0) { take = true; quota--; }
                if (take) {
                    int s = b * PP + j;
                    if (s != pixq) nbr_sm[tid * KK + (kout++)] = s;
                }
            }
        }
        for (; kout < KK; kout++) nbr_sm[tid * KK + kout] = -1;
    }
    __syncthreads();

    // copy neighbor lists to global
    {
        const int4* src = (const int4*)nbr_sm;
        int4* dst = (int4*)&g_nbr[q0g * KK];
#pragma unroll
        for (int i = 0; i < 8; i++) dst[i * 256 + tid] = src[i * 256 + tid];
    }

    // ---- phase B: BN partial stats over this block's 8448 messages ----
    {
        int c4 = (tid & 31) * 4;
        int part = tid >> 5;
        float w64v[4], w65v[4], b1v[4];
#pragma unroll
        for (int u = 0; u < 4; u++) {
            int ch = ch_of_slot(c4 + u);
            w64v[u] = W1[64 * C1 + ch];
            w65v[u] = W1[65 * C1 + ch];
            b1v[u]  = b1[ch];
        }
        float sum[4] = {0.f, 0.f, 0.f, 0.f};
        float sq [4] = {0.f, 0.f, 0.f, 0.f};
        int cnt = 0;
        int m0 = part * 1056;
#pragma unroll 4
        for (int m = m0; m < m0 + 1056; m++) {
            int s; float rx, ry;
            if (m < 8192) {
                s = nbr_sm[m];
                if (s < 0) continue;
                int j = s & 1023;
                int dl = pixl[m >> 5] & 1023;
                rx = ps[j].x - ps[dl].x;
                ry = ps[j].y - ps[dl].y;
            } else {
                s = q0g + (m - 8192);
                rx = 0.f; ry = 0.f;
            }
            cnt++;
            float4 y = *(const float4*)&g_Y[s * C1 + c4];
            float z0 = fmaf(rx, w64v[0], fmaf(ry, w65v[0], y.x + b1v[0]));
            float z1 = fmaf(rx, w64v[1], fmaf(ry, w65v[1], y.y + b1v[1]));
            float z2 = fmaf(rx, w64v[2], fmaf(ry, w65v[2], y.z + b1v[2]));
            float z3 = fmaf(rx, w64v[3], fmaf(ry, w65v[3], y.w + b1v[3]));
            sum[0] += z0; sum[1] += z1; sum[2] += z2; sum[3] += z3;
            sq[0] = fmaf(z0, z0, sq[0]); sq[1] = fmaf(z1, z1, sq[1]);
            sq[2] = fmaf(z2, z2, sq[2]); sq[3] = fmaf(z3, z3, sq[3]);
        }
        int slot = blockIdx.x * 8 + part;
        *(float4*)&g_psum[slot * C1 + c4] = make_float4(sum[0], sum[1], sum[2], sum[3]);
        *(float4*)&g_psq [slot * C1 + c4] = make_float4(sq[0], sq[1], sq[2], sq[3]);
        if ((tid & 31) == 0) g_pcnt[slot] = cnt;
    }
}

// ---------------- kernel 5: reduce stats -> fused BN coefficients ----------
__global__ void k_reduce(const float* __restrict__ W1, const float* __restrict__ b1,
                         const float* __restrict__ gamma1, const float* __restrict__ beta1) {
    int c = blockIdx.x * 8 + (threadIdx.x >> 5);   // slot
    int lane = threadIdx.x & 31;
    double s = 0.0, sq = 0.0;
    long long cnt = 0;
    for (int i = lane; i < NSLOT; i += 32) {
        s  += (double)g_psum[i * C1 + c];
        sq += (double)g_psq [i * C1 + c];
        cnt += g_pcnt[i];
    }
#pragma unroll
    for (int o = 16; o > 0; o >>= 1) {
        s   += __shfl_xor_sync(0xffffffffu, s, o);
        sq  += __shfl_xor_sync(0xffffffffu, sq, o);
        cnt += __shfl_xor_sync(0xffffffffu, cnt, o);
    }
    if (lane == 0) {
        int ch = ch_of_slot(c);
        double mean = s / (double)cnt;
        double var  = sq / (double)cnt - mean * mean;
        float A = gamma1[ch] / sqrtf((float)var + 1e-5f);
        g_coef[c]           = A;
        g_coef[C1 + c]      = W1[64 * C1 + ch] * A;
        g_coef[2 * C1 + c]  = W1[65 * C1 + ch] * A;
        g_coef[3 * C1 + c]  = beta1[ch] + (b1[ch] - (float)mean) * A;
    }
}

// ---------------- kernel 6: main fused (h halves -> tf32 mma -> max) -------
// 8192 blocks x 256 threads; 4 queries per block; 3 blocks/SM.
__global__ void __launch_bounds__(256, 3)
k_main(const float* __restrict__ pos, const float* __restrict__ b2,
       unsigned* __restrict__ out_u) {
    extern __shared__ float sm[];
    float* hs  = sm;                        // [128 edges][HSH], 64 slots per half
    float* W2t = sm + 128 * HSH;            // [64 n][WS] tf32 bits
    float* ex2 = W2t + 64 * WS;
    float* ey2 = ex2 + 128;
    int*   es2 = (int*)(ey2 + 128);
    float* qmx = (float*)(es2 + 128);       // [4 queries][64 cols]

    int tid = threadIdx.x;
    int q0 = blockIdx.x * 4;
    const float NI = __int_as_float(0xff800000);

    // stage W2t from pre-transposed global (coalesced LDG, conflict-free STS)
    for (int i = tid; i < 64 * C1; i += 256)
        W2t[(i >> 7) * WS + (i & 127)] = g_W2t[i];
    if (tid < 128) {
        int q = q0 + (tid >> 5);
        int s = g_nbr[q * KK + (tid & 31)];
        es2[tid] = s;
        float rx = 0.f, ry = 0.f;
        if (s >= 0) {
            int d = g_pix[q];
            rx = pos[2 * s]     - pos[2 * d];
            ry = pos[2 * s + 1] - pos[2 * d + 1];
        }
        ex2[tid] = rx; ey2[tid] = ry;
    }

    // warp tiling: 8 warps = 4 m-groups (1 query, 32 edges) x 2 n-halves (32 cols)
    int lane = tid & 31, w = tid >> 5;
    int g = lane >> 2, t = lane & 3;
    int nh = w & 1, mh = w >> 1;
    int n0 = nh * 32;
    int e0 = mh * 32;

    float d[2][4][4];   // [mt][nt][4]
#pragma unroll
    for (int a1 = 0; a1 < 2; a1++)
#pragma unroll
        for (int a2 = 0; a2 < 4; a2++)
#pragma unroll
            for (int a3 = 0; a3 < 4; a3++) d[a1][a2][a3] = 0.f;

    __syncthreads();

#pragma unroll
    for (int half = 0; half < 2; half++) {
        // ---- h phase: slots [half*64, half*64+64) for all 128 edges ----
        {
            int c4 = (tid & 15) * 4;
            int eg = tid >> 4;
            int sb = half * 64 + c4;
            float4 av = *(const float4*)&g_coef[sb];
            float4 xv = *(const float4*)&g_coef[C1 + sb];
            float4 yv = *(const float4*)&g_coef[2 * C1 + sb];
            float4 bv = *(const float4*)&g_coef[3 * C1 + sb];
#pragma unroll
            for (int e = 0; e < 8; e++) {
                int ee = eg * 8 + e;
                int s = es2[ee];
                float4 h = make_float4(0.f, 0.f, 0.f, 0.f);
                if (s >= 0) {
                    float4 y = *(const float4*)&g_Y[s * C1 + sb];
                    float rx = ex2[ee], ry = ey2[ee];
                    h.x = fmaxf(fmaf(y.x, av.x, fmaf(rx, xv.x, fmaf(ry, yv.x, bv.x))), 0.f);
                    h.y = fmaxf(fmaf(y.y, av.y, fmaf(rx, xv.y, fmaf(ry, yv.y, bv.y))), 0.f);
                    h.z = fmaxf(fmaf(y.z, av.z, fmaf(rx, xv.z, fmaf(ry, yv.z, bv.z))), 0.f);
                    h.w = fmaxf(fmaf(y.w, av.w, fmaf(rx, xv.w, fmaf(ry, yv.w, bv.w))), 0.f);
                }
                float4 ht;
                ht.x = __uint_as_float(f2tf32(h.x));
                ht.y = __uint_as_float(f2tf32(h.y));
                ht.z = __uint_as_float(f2tf32(h.z));
                ht.w = __uint_as_float(f2tf32(h.w));
                *(float4*)&hs[ee * HSH + c4] = ht;
            }
        }
        __syncthreads();

        // ---- mma: 8 k-steps on this half ----
#pragma unroll
        for (int ks = 0; ks < 8; ks++) {
            int kg = half * 64 + ks * 8;      // absolute slot base (for W2t)
            int kh = ks * 8;                  // slot base within hs half
            // B fragments: 4 n-tiles
            unsigned bb[4][2];
#pragma unroll
            for (int nt = 0; nt < 4; nt++) {
                float2 bv = *(const float2*)&W2t[(n0 + nt * 8 + g) * WS + kg + 2 * t];
                bb[nt][0] = __float_as_uint(bv.x);
                bb[nt][1] = __float_as_uint(bv.y);
            }
#pragma unroll
            for (int mt = 0; mt < 2; mt++) {
                const float* hp = hs + (e0 + mt * 16 + g) * HSH + kh + 2 * t;
                float2 alo = *(const float2*)hp;
                float2 ahi = *(const float2*)(hp + 8 * HSH);
                unsigned a0 = __float_as_uint(alo.x);
                unsigned a2 = __float_as_uint(alo.y);
                unsigned a1 = __float_as_uint(ahi.x);
                unsigned a3 = __float_as_uint(ahi.y);
#pragma unroll
                for (int nt = 0; nt < 4; nt++) {
                    asm volatile(
                        "mma.sync.aligned.m16n8k8.row.col.f32.tf32.tf32.f32 "
                        "{%0,%1,%2,%3}, {%4,%5,%6,%7}, {%8,%9}, {%0,%1,%2,%3};"
                        : "+f"(d[mt][nt][0]), "+f"(d[mt][nt][1]),
                          "+f"(d[mt][nt][2]), "+f"(d[mt][nt][3])
                        : "r"(a0), "r"(a1), "r"(a2), "r"(a3),
                          "r"(bb[nt][0]), "r"(bb[nt][1]));
                }
            }
        }
        __syncthreads();   // before next half overwrites hs
    }

    // ---- masked max over this warp's 32 edges (= one query) ----
    {
        float rm[4][2];
#pragma unroll
        for (int nt = 0; nt < 4; nt++) { rm[nt][0] = NI; rm[nt][1] = NI; }
#pragma unroll
        for (int mt = 0; mt < 2; mt++) {
            bool vlo = es2[e0 + mt * 16 + g] >= 0;
            bool vhi = es2[e0 + mt * 16 + 8 + g] >= 0;
#pragma unroll
            for (int nt = 0; nt < 4; nt++) {
                float x0 = vlo ? d[mt][nt][0] : NI;
                float x1 = vlo ? d[mt][nt][1] : NI;
                float x2 = vhi ? d[mt][nt][2] : NI;
                float x3 = vhi ? d[mt][nt][3] : NI;
                rm[nt][0] = fmaxf(rm[nt][0], fmaxf(x0, x2));
                rm[nt][1] = fmaxf(rm[nt][1], fmaxf(x1, x3));
            }
        }
#pragma unroll
        for (int nt = 0; nt < 4; nt++)
#pragma unroll
            for (int j = 0; j < 2; j++) {
                float v = rm[nt][j];
                v = fmaxf(v, __shfl_xor_sync(0xffffffffu, v, 4));
                v = fmaxf(v, __shfl_xor_sync(0xffffffffu, v, 8));
                v = fmaxf(v, __shfl_xor_sync(0xffffffffu, v, 16));
                rm[nt][j] = v;
            }
        if (lane < 4) {
#pragma unroll
            for (int nt = 0; nt < 4; nt++) {
                qmx[mh * 64 + n0 + nt * 8 + 2 * t]     = rm[nt][0];
                qmx[mh * 64 + n0 + nt * 8 + 2 * t + 1] = rm[nt][1];
            }
        }
    }
    __syncthreads();

    // global fold: one atomic per (query, channel)
    {
        float v = qmx[tid];
        if (__float_as_uint(v) != 0xff800000u) {
            int col = tid & 63, qloc = tid >> 6;
            int q = q0 + qloc;
            int P = g_pix[q];
            atomicMax(&out_u[(P >> 10) * (FF * PP) + col * PP + (P & 1023)],
                      encf(v + b2[col]));
        }
    }
}

// ---------------- kernel 7: self-loop messages (target = own node) ---------
__global__ void k_self(const float* __restrict__ W2, const float* __restrict__ b2,
                       unsigned* __restrict__ out_u) {
    extern __shared__ float sm[];
    float* W2s = sm;                 // [128 slot-rows][64]
    float* hsl = sm + 8192;
    float* cfA = hsl + 128 * HSTR2;
    float* cfB = cfA + 128;
    float* b2s = cfB + 128;

    int tid = threadIdx.x;
    int i0 = blockIdx.x * 64;

    for (int i = tid; i < 8192; i += 128) {
        int c = i >> 6, n = i & 63;
        W2s[slot_of_ch(c) * 64 + n] = W2[i];
    }
    cfA[tid] = g_coef[tid];
    cfB[tid] = g_coef[3 * C1 + tid];
    if (tid < 64) b2s[tid] = b2[tid];
    __syncthreads();

    {
        float a = cfA[tid], bb = cfB[tid];
#pragma unroll 4
        for (int e = 0; e < 64; e++)
            hsl[tid * HSTR2 + e] = fmaxf(fmaf(g_Y[(i0 + e) * C1 + tid], a, bb), 0.f);
    }
    __syncthreads();

    int eg = tid & 15, fg = tid >> 4;
    float acc[4][8];
#pragma unroll
    for (int e = 0; e < 4; e++)
#pragma unroll
        for (int f = 0; f < 8; f++) acc[e][f] = 0.f;

    const float* hb = hsl + eg * 4;
    const float* wb = W2s + fg * 8;
    for (int c = 0; c < C1; c++) {
        float4 hv = *(const float4*)(hb + c * HSTR2);
        float4 w0 = *(const float4*)(wb + c * 64);
        float4 w1 = *(const float4*)(wb + c * 64 + 4);
        float hvv[4] = {hv.x, hv.y, hv.z, hv.w};
        float wv[8]  = {w0.x, w0.y, w0.z, w0.w, w1.x, w1.y, w1.z, w1.w};
#pragma unroll
        for (int e = 0; e < 4; e++)
#pragma unroll
            for (int f = 0; f < 8; f++)
                acc[e][f] = fmaf(hvv[e], wv[f], acc[e][f]);
    }

#pragma unroll
    for (int e = 0; e < 4; e++) {
        int node = i0 + eg * 4 + e;
        unsigned base = (unsigned)((node >> 10) * (FF * PP) + (node & 1023));
#pragma unroll
        for (int f = 0; f < 8; f++) {
            float v = acc[e][f] + b2s[fg * 8 + f];
            atomicMax(&out_u[base + (fg * 8 + f) * PP], encf(v));
        }
    }
}

// ---------------- kernel 8: decode in place ----------------
__global__ void k_decode(unsigned* __restrict__ out_u) {
    int i = blockIdx.x * 256 + threadIdx.x;
    if (i < NPTS * FF) {
        unsigned u = out_u[i];
        ((float*)out_u)[i] = decf(u);
    }
}

// ---------------- launch ----------------
extern "C" void kernel_launch(void* const* d_in, const int* in_sizes, int n_in,
                              void* d_out, int out_size) {
    const float* x      = (const float*)d_in[0];
    const float* pos    = (const float*)d_in[1];
    const int*   batch  = (const int*)  d_in[2];
    const float* W1     = (const float*)d_in[3];
    const float* b1     = (const float*)d_in[4];
    const float* gamma1 = (const float*)d_in[5];
    const float* beta1  = (const float*)d_in[6];
    const float* W2     = (const float*)d_in[7];
    const float* b2     = (const float*)d_in[8];
    unsigned* out_u = (unsigned*)d_out;

    cudaFuncSetAttribute(k_main, cudaFuncAttributeMaxDynamicSharedMemorySize, SMEM_MAIN_BYTES);
    cudaFuncSetAttribute(k_self, cudaFuncAttributeMaxDynamicSharedMemorySize, SMEM_SELF_BYTES);

    k_init    <<<(NPTS * FF + 255) / 256, 256>>>(out_u);         // 1
    k_pre     <<<NPTS / 64, 256>>>(x, pos, batch, W1);           // 2
    k_w2      <<<32, 256>>>(W2);                                 // 3
    k_nbrstats<<<NB * 4, 256>>>(pos, W1, b1);                    // 4 <- profiled
    k_reduce  <<<16, 256>>>(W1, b1, gamma1, beta1);              // 5
    k_main    <<<NPTS / 4, 256, SMEM_MAIN_BYTES>>>(pos, b2, out_u); // 6
    k_self    <<<NPTS / 64, 128, SMEM_SELF_BYTES>>>(W2, b2, out_u); // 7
    k_decode  <<<(NPTS * FF + 255) / 256, 256>>>(out_u);         // 8
}

// round 12
// speedup vs baseline: 3.2099x; 1.3847x over previous
#include <cuda_runtime.h>

// ---------------- problem constants ----------------
#define NPTS   32768        // B*P
#define PP     1024         // points per sample
#define NB     32           // batch
#define FF     64           // feature dim
#define KK     32           // max neighbors
#define C1     128          // hidden dim
#define NSLOT  8192         // stat partial slots (1024 blocks x 8)
#define ENC_NEG_INF 0x007FFFFFu
#define CAP    128          // candidate cap in k_nbr
#define GC     8            // spatial grid cells per dim (cell = 0.125 > R = 0.1)

#define HSH 72              // hs stride: 64 slots + 8 pad
#define WS  136             // W2t smem stride: 128 slots + 8 pad
#define SMEM_MAIN_FLOATS (128*HSH + 64*WS + 128 + 128 + 128 + 256)
#define SMEM_MAIN_BYTES  (SMEM_MAIN_FLOATS * 4)

#define HSTR2 72
#define SMEM_SELF_FLOATS (8192 + 128*HSTR2 + 128 + 128 + 64)
#define SMEM_SELF_BYTES  (SMEM_SELF_FLOATS * 4)

// ---------------- device scratch (static, no allocation) ----------------
// hidden dim stored in PERMUTED "slot" space: slot j = 2t + hi <-> channel t + 4*hi
__device__ float    g_Y[NPTS * C1];         // x @ W1[:64], slot cols (16 MB)
__device__ int      g_pix[NPTS];
__device__ int      g_nbr[NPTS * KK];
__device__ float    g_psum[NSLOT * C1];
__device__ float    g_psq [NSLOT * C1];
__device__ int      g_pcnt[NSLOT];
__device__ float    g_coef[4 * C1];         // alpha | w64*a | w65*a | beta+(b1-mean)*a (slot space)
__device__ float    g_W2t[64 * C1];         // W2 transposed [n][slot], tf32 bits

__device__ __forceinline__ int ch_of_slot(int s) {
    int j = s & 7;
    return (s & ~7) | ((j >> 1) + ((j & 1) << 2));
}
__device__ __forceinline__ int slot_of_ch(int c) {
    int r = c & 7;
    int j = (r < 4) ? (r << 1) : ((r << 1) - 7);
    return (c & ~7) | j;
}

__device__ __forceinline__ unsigned encf(float f) {
    unsigned u = __float_as_uint(f);
    return (u & 0x80000000u) ? ~u : (u | 0x80000000u);
}
__device__ __forceinline__ float decf(unsigned u) {
    return (u & 0x80000000u) ? __uint_as_float(u & 0x7fffffffu)
                             : __uint_as_float(~u);
}
__device__ __forceinline__ unsigned f2tf32(float f) {
    unsigned u;
    asm("cvt.rna.tf32.f32 %0, %1;" : "=r"(u) : "f"(f));
    return u;
}

// depth-5 tree argmax over best[32]
__device__ __forceinline__ void tree_max32(const float* best, float& bmax, int& bpos) {
    float m16[16]; int i16[16];
#pragma unroll
    for (int k = 0; k < 16; k++) {
        bool p = best[2*k] >= best[2*k+1];
        m16[k] = p ? best[2*k] : best[2*k+1];
        i16[k] = p ? 2*k : 2*k+1;
    }
    float m8[8]; int i8[8];
#pragma unroll
    for (int k = 0; k < 8; k++) {
        bool p = m16[2*k] >= m16[2*k+1];
        m8[k] = p ? m16[2*k] : m16[2*k+1];
        i8[k] = p ? i16[2*k] : i16[2*k+1];
    }
    float m4[4]; int i4[4];
#pragma unroll
    for (int k = 0; k < 4; k++) {
        bool p = m8[2*k] >= m8[2*k+1];
        m4[k] = p ? m8[2*k] : m8[2*k+1];
        i4[k] = p ? i8[2*k] : i8[2*k+1];
    }
    float m2[2]; int i2[2];
#pragma unroll
    for (int k = 0; k < 2; k++) {
        bool p = m4[2*k] >= m4[2*k+1];
        m2[k] = p ? m4[2*k] : m4[2*k+1];
        i2[k] = p ? i4[2*k] : i4[2*k+1];
    }
    bool p = m2[0] >= m2[1];
    bmax = p ? m2[0] : m2[1];
    bpos = p ? i2[0] : i2[1];
}

// ---------------- kernel 1: init output accumulator ----------------
__global__ void k_init(unsigned* __restrict__ out_u) {
    int i = blockIdx.x * 256 + threadIdx.x;
    if (i < NPTS * FF) out_u[i] = ENC_NEG_INF;
}

// ---------------- kernel 2: pixel index + Y = x @ W1[:64] ----------------
__global__ void k_pre(const float* __restrict__ x, const float* __restrict__ pos,
                      const int* __restrict__ batch, const float* __restrict__ W1) {
    __shared__ float w1s[64 * C1];
    __shared__ float xs[64 * FF];
    int tid = threadIdx.x;
    int p0 = blockIdx.x * 64;

    for (int i = tid; i < 64 * C1; i += 256) {
        int r = i >> 7, sl = i & 127;
        w1s[i] = W1[r * C1 + ch_of_slot(sl)];
    }
    for (int i = tid; i < 64 * FF; i += 256) xs[i] = x[p0 * FF + i];
    if (tid < 64) {
        int i = p0 + tid;
        float px = pos[2 * i], py = pos[2 * i + 1];
        int col = (int)(px * 32.0f); col = min(max(col, 0), 31);
        int row = (int)(py * 32.0f); row = min(max(row, 0), 31);
        g_pix[i] = batch[i] * (NB * NB) + row * 32 + col;
    }
    __syncthreads();

    int pg = tid >> 5;
    int c0 = (tid & 31) * 4;
    float acc[8][4];
#pragma unroll
    for (int p = 0; p < 8; p++)
#pragma unroll
        for (int c = 0; c < 4; c++) acc[p][c] = 0.f;

    for (int r = 0; r < 64; r++) {
        float4 w = *(const float4*)&w1s[r * C1 + c0];
#pragma unroll
        for (int p = 0; p < 8; p++) {
            float xv = xs[(pg * 8 + p) * FF + r];
            acc[p][0] = fmaf(xv, w.x, acc[p][0]);
            acc[p][1] = fmaf(xv, w.y, acc[p][1]);
            acc[p][2] = fmaf(xv, w.z, acc[p][2]);
            acc[p][3] = fmaf(xv, w.w, acc[p][3]);
        }
    }
#pragma unroll
    for (int p = 0; p < 8; p++) {
        int pt = p0 + pg * 8 + p;
        *(float4*)&g_Y[pt * C1 + c0] =
            make_float4(acc[p][0], acc[p][1], acc[p][2], acc[p][3]);
    }
}

// ---------------- kernel 3: W2 -> global transposed slot-space tf32 --------
__global__ void k_w2(const float* __restrict__ W2) {
    int i = blockIdx.x * 256 + threadIdx.x;
    if (i < 64 * C1) {
        int n = i >> 7, sl = i & 127;
        g_W2t[n * C1 + sl] = __uint_as_float(f2tf32(W2[ch_of_slot(sl) * 64 + n]));
    }
}

// ---------------- kernel 4: binned radius K-NN (profiled slot) -------------
// 256 blocks x 128 threads; block owns 128 queries of one batch sample.
// 8x8 spatial grid (cell 0.125 > R=0.1): 3x3 ring provably covers the ball.
__global__ void k_nbr(const float* __restrict__ pos) {
    __shared__ float2 ps[PP];
    __shared__ int cstart[GC * GC + 1];
    __shared__ int ccnt[GC * GC];
    __shared__ int cpts[PP];
    int tid = threadIdx.x;
    int b = blockIdx.x >> 3;
    int qoff = (blockIdx.x & 7) << 7;
    const float2* pb = (const float2*)pos + b * PP;
    for (int i = tid; i < PP; i += 128) ps[i] = pb[i];
    if (tid < GC * GC) ccnt[tid] = 0;
    __syncthreads();

    // bin counts
    for (int j = tid; j < PP; j += 128) {
        int cx = min(max((int)(ps[j].x * GC), 0), GC - 1);
        int cy = min(max((int)(ps[j].y * GC), 0), GC - 1);
        atomicAdd(&ccnt[cy * GC + cx], 1);
    }
    __syncthreads();
    if (tid == 0) {
        int acc = 0;
        for (int i = 0; i < GC * GC; i++) { cstart[i] = acc; acc += ccnt[i]; }
        cstart[GC * GC] = acc;
    }
    __syncthreads();
    if (tid < GC * GC) ccnt[tid] = 0;
    __syncthreads();
    // scatter
    for (int j = tid; j < PP; j += 128) {
        int cx = min(max((int)(ps[j].x * GC), 0), GC - 1);
        int cy = min(max((int)(ps[j].y * GC), 0), GC - 1);
        int cid = cy * GC + cx;
        int p = cstart[cid] + atomicAdd(&ccnt[cid], 1);
        cpts[p] = j;
    }
    __syncthreads();
    // per-cell ascending-j sort (determinism of output order)
    if (tid < GC * GC) {
        int s0 = cstart[tid], s1 = cstart[tid + 1];
        for (int i = s0 + 1; i < s1; i++) {
            int v = cpts[i];
            int k = i - 1;
            while (k >= s0 && cpts[k] > v) { cpts[k + 1] = cpts[k]; k--; }
            cpts[k + 1] = v;
        }
    }
    __syncthreads();

    // ---- query: 1 thread per query over 3x3 cell ring ----
    int ql = qoff + tid;
    int q = b * PP + ql;
    float qx = ps[ql].x, qy = ps[ql].y;
    const float R2 = 0.01f;
    const float INF = __int_as_float(0x7f800000);
    int pixq = g_pix[q];
    int cx0 = min(max((int)(qx * GC), 0), GC - 1);
    int cy0 = min(max((int)(qy * GC), 0), GC - 1);

    float cd2[CAP];
    int   cj [CAP];
    int c = 0;
    for (int cy = max(cy0 - 1, 0); cy <= min(cy0 + 1, GC - 1); cy++)
        for (int cx = max(cx0 - 1, 0); cx <= min(cx0 + 1, GC - 1); cx++) {
            int cid = cy * GC + cx;
            int e1 = cstart[cid + 1];
            for (int p = cstart[cid]; p < e1; p++) {
                int j = cpts[p];
                float dx = __fsub_rn(qx, ps[j].x);
                float dy = __fsub_rn(qy, ps[j].y);
                float d2 = __fadd_rn(__fmul_rn(dx, dx), __fmul_rn(dy, dy));
                if (d2 <= R2) {
                    if (c < CAP) { cd2[c] = d2; cj[c] = j; }
                    c++;
                }
            }
        }

    int kout = 0;
    if (c <= KK) {
        for (int i = 0; i < c; i++) {
            int s = b * PP + cj[i];
            if (s != pixq) g_nbr[q * KK + (kout++)] = s;
        }
    } else if (c <= CAP) {
        float best[32];
#pragma unroll
        for (int k = 0; k < 32; k++) best[k] = cd2[k];
        float bmax; int bpos;
        tree_max32(best, bmax, bpos);
        for (int i = 32; i < c; i++) {
            float d = cd2[i];
            if (d < bmax) {
#pragma unroll
                for (int k = 0; k < 32; k++) best[k] = (k == bpos) ? d : best[k];
                tree_max32(best, bmax, bpos);
            }
        }
        float t = bmax;
        int c1 = 0, nties = 0;
        for (int i = 0; i < c; i++) {
            c1    += (cd2[i] < t) ? 1 : 0;
            nties += (cd2[i] == t) ? 1 : 0;
        }
        int quota = KK - c1;
        if (quota >= nties) {
            for (int i = 0; i < c; i++) {
                if (cd2[i] <= t) {
                    int s = b * PP + cj[i];
                    if (s != pixq) g_nbr[q * KK + (kout++)] = s;
                }
            }
        } else {
            // rare exact-tie path: take quota smallest-j ties (matches top_k)
            for (int i = 0; i < c; i++) {
                bool take = (cd2[i] < t);
                if (!take && cd2[i] == t) {
                    int rank = 0;
                    for (int k2 = 0; k2 < c; k2++)
                        rank += (cd2[k2] == t && cj[k2] < cj[i]) ? 1 : 0;
                    take = (rank < quota);
                }
                if (take) {
                    int s = b * PP + cj[i];
                    if (s != pixq) g_nbr[q * KK + (kout++)] = s;
                }
            }
        }
    } else {
        // overflow fallback (never expected): full streaming scan over sample
        float best[32];
#pragma unroll
        for (int k = 0; k < 32; k++) best[k] = INF;
        float bmax = INF; int bpos = 0;
        for (int j = 0; j < PP; j++) {
            float dx = __fsub_rn(qx, ps[j].x);
            float dy = __fsub_rn(qy, ps[j].y);
            float d2 = __fadd_rn(__fmul_rn(dx, dx), __fmul_rn(dy, dy));
            if (d2 <= R2 && d2 < bmax) {
#pragma unroll
                for (int k = 0; k < 32; k++) best[k] = (k == bpos) ? d2 : best[k];
                tree_max32(best, bmax, bpos);
            }
        }
        float t = bmax;
        int c1 = 0;
        for (int j = 0; j < PP; j++) {
            float dx = __fsub_rn(qx, ps[j].x);
            float dy = __fsub_rn(qy, ps[j].y);
            float d2 = __fadd_rn(__fmul_rn(dx, dx), __fmul_rn(dy, dy));
            c1 += (d2 <= R2 && d2 < t) ? 1 : 0;
        }
        int quota = KK - c1;
        for (int j = 0; j < PP; j++) {
            float dx = __fsub_rn(qx, ps[j].x);
            float dy = __fsub_rn(qy, ps[j].y);
            float d2 = __fadd_rn(__fmul_rn(dx, dx), __fmul_rn(dy, dy));
            if (d2 > R2) continue;
            bool take = false;
            if (d2 < t) take = true;
            else if (d2 == t && quota > 0) { take = true; quota--; }
            if (take) {
                int s = b * PP + j;
                if (s != pixq) g_nbr[q * KK + (kout++)] = s;
            }
        }
    }
    for (; kout < KK; kout++) g_nbr[q * KK + kout] = -1;
}

// ---------------- kernel 5: BN partial stats (1024 blocks, standalone) -----
__global__ void k_stats(const float* __restrict__ pos, const float* __restrict__ W1,
                        const float* __restrict__ b1) {
    __shared__ int   es[1056];
    __shared__ float ex[1056];
    __shared__ float ey[1056];
    int tid = threadIdx.x;
    int q0 = blockIdx.x * 32;

    for (int idx = tid; idx < 1024; idx += 256) {
        int q = q0 + (idx >> 5);
        int s = g_nbr[q * KK + (idx & 31)];
        es[idx] = s;
        float rx = 0.f, ry = 0.f;
        if (s >= 0) {
            int d = g_pix[q];
            rx = pos[2 * s]     - pos[2 * d];
            ry = pos[2 * s + 1] - pos[2 * d + 1];
        }
        ex[idx] = rx; ey[idx] = ry;
    }
    if (tid < 32) { es[1024 + tid] = q0 + tid; ex[1024 + tid] = 0.f; ey[1024 + tid] = 0.f; }
    __syncthreads();

    int c4 = (tid & 31) * 4;
    int part = tid >> 5;            // 8 partials, 132 messages each
    float w64v[4], w65v[4], b1v[4];
#pragma unroll
    for (int u = 0; u < 4; u++) {
        int ch = ch_of_slot(c4 + u);
        w64v[u] = W1[64 * C1 + ch];
        w65v[u] = W1[65 * C1 + ch];
        b1v[u]  = b1[ch];
    }
    float sum[4] = {0.f, 0.f, 0.f, 0.f};
    float sq [4] = {0.f, 0.f, 0.f, 0.f};
    int cnt = 0;
    int m0 = part * 132;
#pragma unroll 4
    for (int m = m0; m < m0 + 132; m++) {
        int s = es[m];
        if (s < 0) continue;
        cnt++;
        float rx = ex[m], ry = ey[m];
        float4 y = *(const float4*)&g_Y[s * C1 + c4];
        float z0 = fmaf(rx, w64v[0], fmaf(ry, w65v[0], y.x + b1v[0]));
        float z1 = fmaf(rx, w64v[1], fmaf(ry, w65v[1], y.y + b1v[1]));
        float z2 = fmaf(rx, w64v[2], fmaf(ry, w65v[2], y.z + b1v[2]));
        float z3 = fmaf(rx, w64v[3], fmaf(ry, w65v[3], y.w + b1v[3]));
        sum[0] += z0; sum[1] += z1; sum[2] += z2; sum[3] += z3;
        sq[0] = fmaf(z0, z0, sq[0]); sq[1] = fmaf(z1, z1, sq[1]);
        sq[2] = fmaf(z2, z2, sq[2]); sq[3] = fmaf(z3, z3, sq[3]);
    }
    int slot = blockIdx.x * 8 + part;
    *(float4*)&g_psum[slot * C1 + c4] = make_float4(sum[0], sum[1], sum[2], sum[3]);
    *(float4*)&g_psq [slot * C1 + c4] = make_float4(sq[0], sq[1], sq[2], sq[3]);
    if ((tid & 31) == 0) g_pcnt[slot] = cnt;
}

// ---------------- kernel 6: reduce stats -> fused BN coefficients ----------
__global__ void k_reduce(const float* __restrict__ W1, const float* __restrict__ b1,
                         const float* __restrict__ gamma1, const float* __restrict__ beta1) {
    int c = blockIdx.x * 8 + (threadIdx.x >> 5);   // slot
    int lane = threadIdx.x & 31;
    double s = 0.0, sq = 0.0;
    long long cnt = 0;
    for (int i = lane; i < NSLOT; i += 32) {
        s  += (double)g_psum[i * C1 + c];
        sq += (double)g_psq [i * C1 + c];
        cnt += g_pcnt[i];
    }
#pragma unroll
    for (int o = 16; o > 0; o >>= 1) {
        s   += __shfl_xor_sync(0xffffffffu, s, o);
        sq  += __shfl_xor_sync(0xffffffffu, sq, o);
        cnt += __shfl_xor_sync(0xffffffffu, cnt, o);
    }
    if (lane == 0) {
        int ch = ch_of_slot(c);
        double mean = s / (double)cnt;
        double var  = sq / (double)cnt - mean * mean;
        float A = gamma1[ch] / sqrtf((float)var + 1e-5f);
        g_coef[c]           = A;
        g_coef[C1 + c]      = W1[64 * C1 + ch] * A;
        g_coef[2 * C1 + c]  = W1[65 * C1 + ch] * A;
        g_coef[3 * C1 + c]  = beta1[ch] + (b1[ch] - (float)mean) * A;
    }
}

// ---------------- kernel 7: main fused (h halves -> tf32 mma -> max) -------
__global__ void __launch_bounds__(256, 3)
k_main(const float* __restrict__ pos, const float* __restrict__ b2,
       unsigned* __restrict__ out_u) {
    extern __shared__ float sm[];
    float* hs  = sm;                        // [128 edges][HSH], 64 slots per half
    float* W2t = sm + 128 * HSH;            // [64 n][WS] tf32 bits
    float* ex2 = W2t + 64 * WS;
    float* ey2 = ex2 + 128;
    int*   es2 = (int*)(ey2 + 128);
    float* qmx = (float*)(es2 + 128);

    int tid = threadIdx.x;
    int q0 = blockIdx.x * 4;
    const float NI = __int_as_float(0xff800000);

    for (int i = tid; i < 64 * C1; i += 256)
        W2t[(i >> 7) * WS + (i & 127)] = g_W2t[i];
    if (tid < 128) {
        int q = q0 + (tid >> 5);
        int s = g_nbr[q * KK + (tid & 31)];
        es2[tid] = s;
        float rx = 0.f, ry = 0.f;
        if (s >= 0) {
            int d = g_pix[q];
            rx = pos[2 * s]     - pos[2 * d];
            ry = pos[2 * s + 1] - pos[2 * d + 1];
        }
        ex2[tid] = rx; ey2[tid] = ry;
    }

    int lane = tid & 31, w = tid >> 5;
    int g = lane >> 2, t = lane & 3;
    int nh = w & 1, mh = w >> 1;
    int n0 = nh * 32;
    int e0 = mh * 32;

    float d[2][4][4];
#pragma unroll
    for (int a1 = 0; a1 < 2; a1++)
#pragma unroll
        for (int a2 = 0; a2 < 4; a2++)
#pragma unroll
            for (int a3 = 0; a3 < 4; a3++) d[a1][a2][a3] = 0.f;

    __syncthreads();

#pragma unroll
    for (int half = 0; half < 2; half++) {
        {
            int c4 = (tid & 15) * 4;
            int eg = tid >> 4;
            int sb = half * 64 + c4;
            float4 av = *(const float4*)&g_coef[sb];
            float4 xv = *(const float4*)&g_coef[C1 + sb];
            float4 yv = *(const float4*)&g_coef[2 * C1 + sb];
            float4 bv = *(const float4*)&g_coef[3 * C1 + sb];
#pragma unroll
            for (int e = 0; e < 8; e++) {
                int ee = eg * 8 + e;
                int s = es2[ee];
                float4 h = make_float4(0.f, 0.f, 0.f, 0.f);
                if (s >= 0) {
                    float4 y = *(const float4*)&g_Y[s * C1 + sb];
                    float rx = ex2[ee], ry = ey2[ee];
                    h.x = fmaxf(fmaf(y.x, av.x, fmaf(rx, xv.x, fmaf(ry, yv.x, bv.x))), 0.f);
                    h.y = fmaxf(fmaf(y.y, av.y, fmaf(rx, xv.y, fmaf(ry, yv.y, bv.y))), 0.f);
                    h.z = fmaxf(fmaf(y.z, av.z, fmaf(rx, xv.z, fmaf(ry, yv.z, bv.z))), 0.f);
                    h.w = fmaxf(fmaf(y.w, av.w, fmaf(rx, xv.w, fmaf(ry, yv.w, bv.w))), 0.f);
                }
                float4 ht;
                ht.x = __uint_as_float(f2tf32(h.x));
                ht.y = __uint_as_float(f2tf32(h.y));
                ht.z = __uint_as_float(f2tf32(h.z));
                ht.w = __uint_as_float(f2tf32(h.w));
                *(float4*)&hs[ee * HSH + c4] = ht;
            }
        }
        __syncthreads();

#pragma unroll
        for (int ks = 0; ks < 8; ks++) {
            int kg = half * 64 + ks * 8;
            int kh = ks * 8;
            unsigned bb[4][2];
#pragma unroll
            for (int nt = 0; nt < 4; nt++) {
                float2 bv = *(const float2*)&W2t[(n0 + nt * 8 + g) * WS + kg + 2 * t];
                bb[nt][0] = __float_as_uint(bv.x);
                bb[nt][1] = __float_as_uint(bv.y);
            }
#pragma unroll
            for (int mt = 0; mt < 2; mt++) {
                const float* hp = hs + (e0 + mt * 16 + g) * HSH + kh + 2 * t;
                float2 alo = *(const float2*)hp;
                float2 ahi = *(const float2*)(hp + 8 * HSH);
                unsigned a0 = __float_as_uint(alo.x);
                unsigned a2 = __float_as_uint(alo.y);
                unsigned a1 = __float_as_uint(ahi.x);
                unsigned a3 = __float_as_uint(ahi.y);
#pragma unroll
                for (int nt = 0; nt < 4; nt++) {
                    asm volatile(
                        "mma.sync.aligned.m16n8k8.row.col.f32.tf32.tf32.f32 "
                        "{%0,%1,%2,%3}, {%4,%5,%6,%7}, {%8,%9}, {%0,%1,%2,%3};"
                        : "+f"(d[mt][nt][0]), "+f"(d[mt][nt][1]),
                          "+f"(d[mt][nt][2]), "+f"(d[mt][nt][3])
                        : "r"(a0), "r"(a1), "r"(a2), "r"(a3),
                          "r"(bb[nt][0]), "r"(bb[nt][1]));
                }
            }
        }
        __syncthreads();
    }

    {
        float rm[4][2];
#pragma unroll
        for (int nt = 0; nt < 4; nt++) { rm[nt][0] = NI; rm[nt][1] = NI; }
#pragma unroll
        for (int mt = 0; mt < 2; mt++) {
            bool vlo = es2[e0 + mt * 16 + g] >= 0;
            bool vhi = es2[e0 + mt * 16 + 8 + g] >= 0;
#pragma unroll
            for (int nt = 0; nt < 4; nt++) {
                float x0 = vlo ? d[mt][nt][0] : NI;
                float x1 = vlo ? d[mt][nt][1] : NI;
                float x2 = vhi ? d[mt][nt][2] : NI;
                float x3 = vhi ? d[mt][nt][3] : NI;
                rm[nt][0] = fmaxf(rm[nt][0], fmaxf(x0, x2));
                rm[nt][1] = fmaxf(rm[nt][1], fmaxf(x1, x3));
            }
        }
#pragma unroll
        for (int nt = 0; nt < 4; nt++)
#pragma unroll
            for (int j = 0; j < 2; j++) {
                float v = rm[nt][j];
                v = fmaxf(v, __shfl_xor_sync(0xffffffffu, v, 4));
                v = fmaxf(v, __shfl_xor_sync(0xffffffffu, v, 8));
                v = fmaxf(v, __shfl_xor_sync(0xffffffffu, v, 16));
                rm[nt][j] = v;
            }
        if (lane < 4) {
#pragma unroll
            for (int nt = 0; nt < 4; nt++) {
                qmx[mh * 64 + n0 + nt * 8 + 2 * t]     = rm[nt][0];
                qmx[mh * 64 + n0 + nt * 8 + 2 * t + 1] = rm[nt][1];
            }
        }
    }
    __syncthreads();

    {
        float v = qmx[tid];
        if (__float_as_uint(v) != 0xff800000u) {
            int col = tid & 63, qloc = tid >> 6;
            int q = q0 + qloc;
            int P = g_pix[q];
            atomicMax(&out_u[(P >> 10) * (FF * PP) + col * PP + (P & 1023)],
                      encf(v + b2[col]));
        }
    }
}

// ---------------- kernel 8: self-loop messages (target = own node) ---------
__global__ void k_self(const float* __restrict__ W2, const float* __restrict__ b2,
                       unsigned* __restrict__ out_u) {
    extern __shared__ float sm[];
    float* W2s = sm;
    float* hsl = sm + 8192;
    float* cfA = hsl + 128 * HSTR2;
    float* cfB = cfA + 128;
    float* b2s = cfB + 128;

    int tid = threadIdx.x;
    int i0 = blockIdx.x * 64;

    for (int i = tid; i < 8192; i += 128) {
        int c = i >> 6, n = i & 63;
        W2s[slot_of_ch(c) * 64 + n] = W2[i];
    }
    cfA[tid] = g_coef[tid];
    cfB[tid] = g_coef[3 * C1 + tid];
    if (tid < 64) b2s[tid] = b2[tid];
    __syncthreads();

    {
        float a = cfA[tid], bb = cfB[tid];
#pragma unroll 4
        for (int e = 0; e < 64; e++)
            hsl[tid * HSTR2 + e] = fmaxf(fmaf(g_Y[(i0 + e) * C1 + tid], a, bb), 0.f);
    }
    __syncthreads();

    int eg = tid & 15, fg = tid >> 4;
    float acc[4][8];
#pragma unroll
    for (int e = 0; e < 4; e++)
#pragma unroll
        for (int f = 0; f < 8; f++) acc[e][f] = 0.f;

    const float* hb = hsl + eg * 4;
    const float* wb = W2s + fg * 8;
    for (int c = 0; c < C1; c++) {
        float4 hv = *(const float4*)(hb + c * HSTR2);
        float4 w0 = *(const float4*)(wb + c * 64);
        float4 w1 = *(const float4*)(wb + c * 64 + 4);
        float hvv[4] = {hv.x, hv.y, hv.z, hv.w};
        float wv[8]  = {w0.x, w0.y, w0.z, w0.w, w1.x, w1.y, w1.z, w1.w};
#pragma unroll
        for (int e = 0; e < 4; e++)
#pragma unroll
            for (int f = 0; f < 8; f++)
                acc[e][f] = fmaf(hvv[e], wv[f], acc[e][f]);
    }

#pragma unroll
    for (int e = 0; e < 4; e++) {
        int node = i0 + eg * 4 + e;
        unsigned base = (unsigned)((node >> 10) * (FF * PP) + (node & 1023));
#pragma unroll
        for (int f = 0; f < 8; f++) {
            float v = acc[e][f] + b2s[fg * 8 + f];
            atomicMax(&out_u[base + (fg * 8 + f) * PP], encf(v));
        }
    }
}

// ---------------- kernel 9: decode in place ----------------
__global__ void k_decode(unsigned* __restrict__ out_u) {
    int i = blockIdx.x * 256 + threadIdx.x;
    if (i < NPTS * FF) {
        unsigned u = out_u[i];
        ((float*)out_u)[i] = decf(u);
    }
}

// ---------------- launch ----------------
extern "C" void kernel_launch(void* const* d_in, const int* in_sizes, int n_in,
                              void* d_out, int out_size) {
    const float* x      = (const float*)d_in[0];
    const float* pos    = (const float*)d_in[1];
    const int*   batch  = (const int*)  d_in[2];
    const float* W1     = (const float*)d_in[3];
    const float* b1     = (const float*)d_in[4];
    const float* gamma1 = (const float*)d_in[5];
    const float* beta1  = (const float*)d_in[6];
    const float* W2     = (const float*)d_in[7];
    const float* b2     = (const float*)d_in[8];
    unsigned* out_u = (unsigned*)d_out;

    cudaFuncSetAttribute(k_main, cudaFuncAttributeMaxDynamicSharedMemorySize, SMEM_MAIN_BYTES);
    cudaFuncSetAttribute(k_self, cudaFuncAttributeMaxDynamicSharedMemorySize, SMEM_SELF_BYTES);

    k_init  <<<(NPTS * FF + 255) / 256, 256>>>(out_u);            // 1
    k_pre   <<<NPTS / 64, 256>>>(x, pos, batch, W1);              // 2
    k_w2    <<<32, 256>>>(W2);                                    // 3
    k_nbr   <<<NPTS / 128, 128>>>(pos);                           // 4 <- profiled
    k_stats <<<NPTS / 32, 256>>>(pos, W1, b1);                    // 5
    k_reduce<<<16, 256>>>(W1, b1, gamma1, beta1);                 // 6
    k_main  <<<NPTS / 4, 256, SMEM_MAIN_BYTES>>>(pos, b2, out_u); // 7
    k_self  <<<NPTS / 64, 128, SMEM_SELF_BYTES>>>(W2, b2, out_u); // 8
    k_decode<<<(NPTS * FF + 255) / 256, 256>>>(out_u);            // 9
}